// round 1
// baseline (speedup 1.0000x reference)
#include <cuda_runtime.h>
#include <math.h>

#define NN 100000
#define NE 1600000
#define DH 128

// ---------------- device scratch (no allocations allowed) ----------------
__device__ int    g_is64;
__device__ int    g_deg[NN];
__device__ float  g_dinv[NN];
__device__ float4 g_agg[(size_t)NN * 32];     // [node][128] as float4x32, 51.2MB
__device__ float  g_wp[DH * 256];             // folded weights [k][0:128]=Wz', [k][128:256]=Wh'

// ---------------- dtype detection for edge_index (int64 vs int32) --------
__global__ void k_detect(const unsigned int* __restrict__ e) {
    if (threadIdx.x == 0) {
        int ok = 1;
#pragma unroll
        for (int i = 0; i < 64; i++) ok &= (e[2 * i + 1] == 0u);
        g_is64 = ok;   // all high words zero -> int64 (ids < 2^31); random int32 ids can't all be 0
    }
}

// ---------------- fold weights: Wz' = Wz @ lzW[:128], Wh' = Wh @ lhW[:128]
__global__ void k_wp(const float* __restrict__ Wz, const float* __restrict__ lzW,
                     const float* __restrict__ Wh, const float* __restrict__ lhW) {
    int k = blockIdx.x;        // 0..127 (input dim)
    int half = blockIdx.y;     // 0: z, 1: h
    int j = threadIdx.x;       // 0..127 (output dim)
    const float* W = half ? Wh : Wz;
    const float* L = half ? lhW : lzW;
    float acc = 0.f;
#pragma unroll 4
    for (int c = 0; c < DH; c++) acc += W[k * DH + c] * L[c * DH + j];
    g_wp[k * 256 + half * DH + j] = acc;
}

// ---------------- degree ----------------
__global__ void k_zero_deg() {
    int i = blockIdx.x * blockDim.x + threadIdx.x;
    if (i < NN) g_deg[i] = 0;
}

__global__ void k_deg(const void* __restrict__ e) {
    int i = blockIdx.x * blockDim.x + threadIdx.x;
    if (i >= NE) return;
    int d;
    if (g_is64) d = (int)((const long long*)e)[(long long)NE + i];
    else        d = ((const int*)e)[NE + i];
    atomicAdd(&g_deg[d], 1);
}

__global__ void k_dinv() {
    int i = blockIdx.x * blockDim.x + threadIdx.x;
    if (i < NN) g_dinv[i] = rsqrtf((float)g_deg[i] + 2.0f);
}

// ---------------- agg init with self-loop term: agg[i] = 2*dinv[i]^2 * x[i]
__global__ void k_agg_init(const float4* __restrict__ x4) {
    long long t = (long long)blockIdx.x * blockDim.x + threadIdx.x;
    if (t >= (long long)NN * 32) return;
    int node = (int)(t >> 5);
    float di = g_dinv[node];
    float s = 2.0f * di * di;
    float4 v = x4[t];
    v.x *= s; v.y *= s; v.z *= s; v.w *= s;
    g_agg[t] = v;
}

// ---------------- edge aggregation: agg[dst] += x[src]*dinv[src]*dinv[dst]
// one warp per edge; lane i handles float4 i (32*4 = 128 floats)
__global__ void __launch_bounds__(256) k_edge(const float4* __restrict__ x4,
                                              const void* __restrict__ e) {
    int w = (blockIdx.x * blockDim.x + threadIdx.x) >> 5;
    int lane = threadIdx.x & 31;
    if (w >= NE) return;
    int s, d;
    if (g_is64) {
        s = (int)((const long long*)e)[w];
        d = (int)((const long long*)e)[(long long)NE + w];
    } else {
        s = ((const int*)e)[w];
        d = ((const int*)e)[NE + w];
    }
    float norm = g_dinv[s] * g_dinv[d];
    float4 v = x4[(long long)s * 32 + lane];
    float4* p = &g_agg[(long long)d * 32 + lane];
    asm volatile("red.global.add.v4.f32 [%0], {%1,%2,%3,%4};" ::
                 "l"(p), "f"(v.x * norm), "f"(v.y * norm),
                 "f"(v.z * norm), "f"(v.w * norm) : "memory");
}

// ---------------- fused GEMM (agg @ [Wz'|Wh']) + gate epilogue + final dot
// block = 256 threads, computes 64 rows x 256 cols.
// thread (tx,ty): tx=tid&15, ty=tid>>4; rows ty*4+r; cols j = u*16+tx (z) and 128+u*16+tx (t)
#define BM 64
#define BK 8
__global__ void __launch_bounds__(256) k_gemm(
    const float* __restrict__ lzb, const float* __restrict__ lhb,
    const float* __restrict__ w2, const float* __restrict__ b2,
    float* __restrict__ out)
{
    __shared__ float sA[BK][BM];
    __shared__ float sB[BK][256];
    int tid = threadIdx.x;
    int tx = tid & 15;
    int ty = tid >> 4;
    int rowBase = blockIdx.x * BM;
    const float* A = (const float*)g_agg;   // [NN][128] row-major

    float accZ[4][8], accT[4][8];
#pragma unroll
    for (int r = 0; r < 4; r++)
#pragma unroll
        for (int u = 0; u < 8; u++) { accZ[r][u] = 0.f; accT[r][u] = 0.f; }

    for (int k0 = 0; k0 < DH; k0 += BK) {
        // A tile: 64x8 = 512 floats, 1 float2 per thread, stored transposed
        {
            int m = tid >> 2;           // 0..63
            int kk = (tid & 3) * 2;     // 0,2,4,6
            int gm = rowBase + m;
            float2 av = make_float2(0.f, 0.f);
            if (gm < NN) av = *(const float2*)&A[(long long)gm * DH + k0 + kk];
            sA[kk][m] = av.x;
            sA[kk + 1][m] = av.y;
        }
        // B tile: 8x256 = 2048 floats, 2 float4 per thread
        {
#pragma unroll
            for (int i = 0; i < 2; i++) {
                int t = tid * 2 + i;       // 0..511
                int kk = t >> 6;           // 0..7
                int j = (t & 63) * 4;      // 0..252
                float4 bv = *(const float4*)&g_wp[(k0 + kk) * 256 + j];
                sB[kk][j] = bv.x; sB[kk][j + 1] = bv.y;
                sB[kk][j + 2] = bv.z; sB[kk][j + 3] = bv.w;
            }
        }
        __syncthreads();
#pragma unroll
        for (int k = 0; k < BK; k++) {
            float a0 = sA[k][ty * 4 + 0];
            float a1 = sA[k][ty * 4 + 1];
            float a2 = sA[k][ty * 4 + 2];
            float a3 = sA[k][ty * 4 + 3];
#pragma unroll
            for (int u = 0; u < 8; u++) {
                float bz_ = sB[k][u * 16 + tx];
                float bt_ = sB[k][128 + u * 16 + tx];
                accZ[0][u] += a0 * bz_; accZ[1][u] += a1 * bz_;
                accZ[2][u] += a2 * bz_; accZ[3][u] += a3 * bz_;
                accT[0][u] += a0 * bt_; accT[1][u] += a1 * bt_;
                accT[2][u] += a2 * bt_; accT[3][u] += a3 * bt_;
            }
        }
        __syncthreads();
    }

    // epilogue: p[r] = sum_j (1-sigmoid(u_j+lzb_j)) * tanh(v_j+lhb_j) * w2_j
    float p[4] = {0.f, 0.f, 0.f, 0.f};
#pragma unroll
    for (int u = 0; u < 8; u++) {
        int j = u * 16 + tx;
        float bzb = lzb[j];
        float bhb = lhb[j];
        float w = w2[j];
#pragma unroll
        for (int r = 0; r < 4; r++) {
            float z = 1.f / (1.f + expf(-(accZ[r][u] + bzb)));
            float t = tanhf(accT[r][u] + bhb);
            p[r] += (1.f - z) * t * w;
        }
    }
    // reduce over the 16 tx lanes (contiguous within each half-warp)
#pragma unroll
    for (int off = 8; off >= 1; off >>= 1)
#pragma unroll
        for (int r = 0; r < 4; r++)
            p[r] += __shfl_down_sync(0xffffffffu, p[r], off, 16);

    if (tx == 0) {
        float bb = b2[0];
#pragma unroll
        for (int r = 0; r < 4; r++) {
            int row = rowBase + ty * 4 + r;
            if (row < NN) out[row] = p[r] + bb;
        }
    }
}

// ---------------- launcher ----------------
// metadata order: x, edge_index, Wz, bz, Wr, br, Wh, bh,
//                 lzW, lzb, lrW, lrb, lhW, lhb, W2, b2
extern "C" void kernel_launch(void* const* d_in, const int* in_sizes, int n_in,
                              void* d_out, int out_size) {
    const float4* x4  = (const float4*)d_in[0];
    const void*   ei  = d_in[1];
    const float*  Wz  = (const float*)d_in[2];
    const float*  Wh  = (const float*)d_in[6];
    const float*  lzW = (const float*)d_in[8];
    const float*  lzb = (const float*)d_in[9];
    const float*  lhW = (const float*)d_in[12];
    const float*  lhb = (const float*)d_in[13];
    const float*  W2  = (const float*)d_in[14];
    const float*  b2  = (const float*)d_in[15];
    float* out = (float*)d_out;

    k_detect<<<1, 32>>>((const unsigned int*)ei);
    k_wp<<<dim3(DH, 2), DH>>>(Wz, lzW, Wh, lhW);
    k_zero_deg<<<(NN + 255) / 256, 256>>>();
    k_deg<<<(NE + 255) / 256, 256>>>(ei);
    k_dinv<<<(NN + 255) / 256, 256>>>();
    k_agg_init<<<(NN * 32 + 255) / 256, 256>>>(x4);
    k_edge<<<(NE * 32 + 255) / 256, 256>>>(x4, ei);
    k_gemm<<<(NN + BM - 1) / BM, 256>>>(lzb, lhb, W2, b2, out);
}

// round 2
// speedup vs baseline: 1.3493x; 1.3493x over previous
#include <cuda_runtime.h>
#include <math.h>

#define NN 100000
#define NE 1600000
#define DH 128
#define SCAN_B 1024
#define NB ((NN + SCAN_B - 1) / SCAN_B)   // 98

// ---------------- device scratch (no allocations allowed) ----------------
__device__ int    g_is64;
__device__ int    g_deg[NN];
__device__ int    g_cur[NN];
__device__ int    g_scan[NB * SCAN_B];    // padded inclusive scan
__device__ int    g_bsum[NB];
__device__ int    g_boff[NB];
__device__ int    g_off[NN + 1];
__device__ int    g_csr[NE];              // src ids grouped by dst, 6.4MB
__device__ float  g_dinv[NN];
__device__ float4 g_xs[(size_t)NN * 32];  // dinv-scaled x, 51.2MB
__device__ float4 g_agg[(size_t)NN * 32]; // aggregated features, 51.2MB
__device__ float  g_wp[DH * 256];         // folded weights [k][0:128]=Wz', [k][128:256]=Wh'

// ---------------- dtype detection for edge_index (int64 vs int32) --------
__global__ void k_detect(const unsigned int* __restrict__ e) {
    if (threadIdx.x == 0) {
        int ok = 1;
#pragma unroll
        for (int i = 0; i < 64; i++) ok &= (e[2 * i + 1] == 0u);
        g_is64 = ok;
    }
}

// ---------------- fold weights: Wz' = Wz @ lzW[:128], Wh' = Wh @ lhW[:128]
__global__ void k_wp(const float* __restrict__ Wz, const float* __restrict__ lzW,
                     const float* __restrict__ Wh, const float* __restrict__ lhW) {
    int k = blockIdx.x;
    int half = blockIdx.y;
    int j = threadIdx.x;
    const float* W = half ? Wh : Wz;
    const float* L = half ? lhW : lzW;
    float acc = 0.f;
#pragma unroll 4
    for (int c = 0; c < DH; c++) acc += W[k * DH + c] * L[c * DH + j];
    g_wp[k * 256 + half * DH + j] = acc;
}

// ---------------- init counters ----------------
__global__ void k_zero() {
    int i = blockIdx.x * blockDim.x + threadIdx.x;
    if (i < NN) { g_deg[i] = 0; g_cur[i] = 0; }
}

// ---------------- degree (dst only) ----------------
__global__ void k_deg(const void* __restrict__ e) {
    int i = blockIdx.x * blockDim.x + threadIdx.x;
    if (i >= NE) return;
    int d;
    if (g_is64) d = (int)((const long long*)e)[(long long)NE + i];
    else        d = ((const int*)e)[NE + i];
    atomicAdd(&g_deg[d], 1);
}

__global__ void k_dinv() {
    int i = blockIdx.x * blockDim.x + threadIdx.x;
    if (i < NN) g_dinv[i] = rsqrtf((float)g_deg[i] + 2.0f);
}

// ---------------- xs = dinv * x ----------------
__global__ void k_xs(const float4* __restrict__ x4) {
    long long t = (long long)blockIdx.x * blockDim.x + threadIdx.x;
    if (t >= (long long)NN * 32) return;
    int node = (int)(t >> 5);
    float s = g_dinv[node];
    float4 v = x4[t];
    v.x *= s; v.y *= s; v.z *= s; v.w *= s;
    g_xs[t] = v;
}

// ---------------- prefix scan of degrees (3 phases) ----------------
__global__ void k_scan1() {
    __shared__ int sbuf[SCAN_B];
    int tid = threadIdx.x;
    int i = blockIdx.x * SCAN_B + tid;
    int v = (i < NN) ? g_deg[i] : 0;
    sbuf[tid] = v;
    __syncthreads();
#pragma unroll
    for (int ofs = 1; ofs < SCAN_B; ofs <<= 1) {
        int t = (tid >= ofs) ? sbuf[tid - ofs] : 0;
        __syncthreads();
        sbuf[tid] += t;
        __syncthreads();
    }
    g_scan[blockIdx.x * SCAN_B + tid] = sbuf[tid];
    if (tid == SCAN_B - 1) g_bsum[blockIdx.x] = sbuf[tid];
}

__global__ void k_scan2() {
    if (threadIdx.x == 0) {
        int run = 0;
        for (int b = 0; b < NB; b++) { g_boff[b] = run; run += g_bsum[b]; }
    }
}

__global__ void k_scan3() {
    int i = blockIdx.x * blockDim.x + threadIdx.x;
    if (i < NN) g_off[i] = g_scan[i] - g_deg[i] + g_boff[i >> 10];  // exclusive
    if (i == NN) g_off[NN] = NE;
}

// ---------------- fill CSR: group edge srcs by dst ----------------
__global__ void k_fill(const void* __restrict__ e) {
    int i = blockIdx.x * blockDim.x + threadIdx.x;
    if (i >= NE) return;
    int s, d;
    if (g_is64) {
        s = (int)((const long long*)e)[i];
        d = (int)((const long long*)e)[(long long)NE + i];
    } else {
        s = ((const int*)e)[i];
        d = ((const int*)e)[NE + i];
    }
    int pos = atomicAdd(&g_cur[d], 1);
    g_csr[g_off[d] + pos] = s;
}

// ---------------- gather: one warp per dst node, no atomics ----------------
__global__ void __launch_bounds__(256) k_gather() {
    int n = (blockIdx.x * blockDim.x + threadIdx.x) >> 5;
    int lane = threadIdx.x & 31;
    if (n >= NN) return;
    int j = g_off[n];
    int jend = g_off[n + 1];
    float4 self = g_xs[(long long)n * 32 + lane];
    float4 a0 = make_float4(2.f * self.x, 2.f * self.y, 2.f * self.z, 2.f * self.w);
    float4 a1 = make_float4(0.f, 0.f, 0.f, 0.f);
    for (; j + 4 <= jend; j += 4) {
        int s0 = __ldcs(&g_csr[j]);
        int s1 = __ldcs(&g_csr[j + 1]);
        int s2 = __ldcs(&g_csr[j + 2]);
        int s3 = __ldcs(&g_csr[j + 3]);
        float4 v0 = g_xs[(long long)s0 * 32 + lane];
        float4 v1 = g_xs[(long long)s1 * 32 + lane];
        float4 v2 = g_xs[(long long)s2 * 32 + lane];
        float4 v3 = g_xs[(long long)s3 * 32 + lane];
        a0.x += v0.x + v1.x; a0.y += v0.y + v1.y; a0.z += v0.z + v1.z; a0.w += v0.w + v1.w;
        a1.x += v2.x + v3.x; a1.y += v2.y + v3.y; a1.z += v2.z + v3.z; a1.w += v2.w + v3.w;
    }
    for (; j < jend; j++) {
        int s = __ldcs(&g_csr[j]);
        float4 v = g_xs[(long long)s * 32 + lane];
        a1.x += v.x; a1.y += v.y; a1.z += v.z; a1.w += v.w;
    }
    float di = g_dinv[n];
    float4 o;
    o.x = di * (a0.x + a1.x); o.y = di * (a0.y + a1.y);
    o.z = di * (a0.z + a1.z); o.w = di * (a0.w + a1.w);
    __stcs(&g_agg[(long long)n * 32 + lane], o);
}

// ---------------- fused GEMM (agg @ [Wz'|Wh']) + gate epilogue + final dot
#define BM 64
#define BK 8
__global__ void __launch_bounds__(256) k_gemm(
    const float* __restrict__ lzb, const float* __restrict__ lhb,
    const float* __restrict__ w2, const float* __restrict__ b2,
    float* __restrict__ out)
{
    __shared__ float sA[BK][BM];
    __shared__ float sB[BK][256];
    int tid = threadIdx.x;
    int tx = tid & 15;
    int ty = tid >> 4;
    int rowBase = blockIdx.x * BM;
    const float* A = (const float*)g_agg;

    float accZ[4][8], accT[4][8];
#pragma unroll
    for (int r = 0; r < 4; r++)
#pragma unroll
        for (int u = 0; u < 8; u++) { accZ[r][u] = 0.f; accT[r][u] = 0.f; }

    for (int k0 = 0; k0 < DH; k0 += BK) {
        {
            int m = tid >> 2;
            int kk = (tid & 3) * 2;
            int gm = rowBase + m;
            float2 av = make_float2(0.f, 0.f);
            if (gm < NN) av = *(const float2*)&A[(long long)gm * DH + k0 + kk];
            sA[kk][m] = av.x;
            sA[kk + 1][m] = av.y;
        }
        {
#pragma unroll
            for (int i = 0; i < 2; i++) {
                int t = tid * 2 + i;
                int kk = t >> 6;
                int jj = (t & 63) * 4;
                float4 bv = *(const float4*)&g_wp[(k0 + kk) * 256 + jj];
                sB[kk][jj] = bv.x; sB[kk][jj + 1] = bv.y;
                sB[kk][jj + 2] = bv.z; sB[kk][jj + 3] = bv.w;
            }
        }
        __syncthreads();
#pragma unroll
        for (int k = 0; k < BK; k++) {
            float a0 = sA[k][ty * 4 + 0];
            float a1 = sA[k][ty * 4 + 1];
            float a2 = sA[k][ty * 4 + 2];
            float a3 = sA[k][ty * 4 + 3];
#pragma unroll
            for (int u = 0; u < 8; u++) {
                float bz_ = sB[k][u * 16 + tx];
                float bt_ = sB[k][128 + u * 16 + tx];
                accZ[0][u] += a0 * bz_; accZ[1][u] += a1 * bz_;
                accZ[2][u] += a2 * bz_; accZ[3][u] += a3 * bz_;
                accT[0][u] += a0 * bt_; accT[1][u] += a1 * bt_;
                accT[2][u] += a2 * bt_; accT[3][u] += a3 * bt_;
            }
        }
        __syncthreads();
    }

    float p[4] = {0.f, 0.f, 0.f, 0.f};
#pragma unroll
    for (int u = 0; u < 8; u++) {
        int jj = u * 16 + tx;
        float bzb = lzb[jj];
        float bhb = lhb[jj];
        float w = w2[jj];
#pragma unroll
        for (int r = 0; r < 4; r++) {
            float z = 1.f / (1.f + expf(-(accZ[r][u] + bzb)));
            float t = tanhf(accT[r][u] + bhb);
            p[r] += (1.f - z) * t * w;
        }
    }
#pragma unroll
    for (int off = 8; off >= 1; off >>= 1)
#pragma unroll
        for (int r = 0; r < 4; r++)
            p[r] += __shfl_down_sync(0xffffffffu, p[r], off, 16);

    if (tx == 0) {
        float bb = b2[0];
#pragma unroll
        for (int r = 0; r < 4; r++) {
            int row = rowBase + ty * 4 + r;
            if (row < NN) out[row] = p[r] + bb;
        }
    }
}

// ---------------- launcher ----------------
// metadata order: x, edge_index, Wz, bz, Wr, br, Wh, bh,
//                 lzW, lzb, lrW, lrb, lhW, lhb, W2, b2
extern "C" void kernel_launch(void* const* d_in, const int* in_sizes, int n_in,
                              void* d_out, int out_size) {
    const float4* x4  = (const float4*)d_in[0];
    const void*   ei  = d_in[1];
    const float*  Wz  = (const float*)d_in[2];
    const float*  Wh  = (const float*)d_in[6];
    const float*  lzW = (const float*)d_in[8];
    const float*  lzb = (const float*)d_in[9];
    const float*  lhW = (const float*)d_in[12];
    const float*  lhb = (const float*)d_in[13];
    const float*  W2  = (const float*)d_in[14];
    const float*  b2  = (const float*)d_in[15];
    float* out = (float*)d_out;

    k_detect<<<1, 32>>>((const unsigned int*)ei);
    k_wp<<<dim3(DH, 2), DH>>>(Wz, lzW, Wh, lhW);
    k_zero<<<(NN + 255) / 256, 256>>>();
    k_deg<<<(NE + 255) / 256, 256>>>(ei);
    k_dinv<<<(NN + 255) / 256, 256>>>();
    k_xs<<<(NN * 32 + 255) / 256, 256>>>(x4);
    k_scan1<<<NB, SCAN_B>>>();
    k_scan2<<<1, 32>>>();
    k_scan3<<<(NN + 256) / 256, 256>>>();
    k_fill<<<(NE + 255) / 256, 256>>>(ei);
    k_gather<<<(NN * 32 + 255) / 256, 256>>>();
    k_gemm<<<(NN + BM - 1) / BM, 256>>>(lzb, lhb, W2, b2, out);
}

// round 3
// speedup vs baseline: 1.5663x; 1.1608x over previous
#include <cuda_runtime.h>
#include <cuda_fp16.h>
#include <math.h>

#define NN 100000
#define NE 1600000
#define DH 128
#define SCAN_B 1024
#define NB ((NN + SCAN_B - 1) / SCAN_B)   // 98

// ---------------- device scratch (no allocations allowed) ----------------
__device__ int     g_is64;
__device__ int     g_deg[NN];
__device__ int     g_cur[NN];
__device__ int     g_scan[NB * SCAN_B];
__device__ int     g_bsum[NB];
__device__ int     g_boff[NB];
__device__ int     g_off[NN + 1];
__device__ int     g_csr[NE];                 // src ids grouped by dst, 6.4MB
__device__ float   g_dinv[NN];
__device__ __half2 g_xsh[(size_t)NN * 64];    // dinv-scaled x in fp16, 25.6MB
__device__ float4  g_agg[(size_t)NN * 32];    // aggregated features fp32, 51.2MB
__device__ float   g_wp[DH * 256];            // folded weights [k][0:128]=Wz', [k][128:256]=Wh'

// ---------------- packed fp32x2 FMA (Blackwell) ----------------
__device__ __forceinline__ void ffma2(float2& d, const float2& a, const float2& b) {
    asm("fma.rn.f32x2 %0, %1, %2, %0;"
        : "+l"(*reinterpret_cast<unsigned long long*>(&d))
        : "l"(*reinterpret_cast<const unsigned long long*>(&a)),
          "l"(*reinterpret_cast<const unsigned long long*>(&b)));
}

// ---------------- dtype detection for edge_index (int64 vs int32) --------
__global__ void k_detect(const unsigned int* __restrict__ e) {
    if (threadIdx.x == 0) {
        int ok = 1;
#pragma unroll
        for (int i = 0; i < 64; i++) ok &= (e[2 * i + 1] == 0u);
        g_is64 = ok;
    }
}

// ---------------- fold weights: Wz' = Wz @ lzW[:128], Wh' = Wh @ lhW[:128]
__global__ void k_wp(const float* __restrict__ Wz, const float* __restrict__ lzW,
                     const float* __restrict__ Wh, const float* __restrict__ lhW) {
    int k = blockIdx.x;
    int half = blockIdx.y;
    int j = threadIdx.x;
    const float* W = half ? Wh : Wz;
    const float* L = half ? lhW : lzW;
    float acc = 0.f;
#pragma unroll 4
    for (int c = 0; c < DH; c++) acc += W[k * DH + c] * L[c * DH + j];
    g_wp[k * 256 + half * DH + j] = acc;
}

// ---------------- init counters ----------------
__global__ void k_zero() {
    int i = blockIdx.x * blockDim.x + threadIdx.x;
    if (i < NN) { g_deg[i] = 0; g_cur[i] = 0; }
}

// ---------------- degree (dst only) ----------------
__global__ void k_deg(const void* __restrict__ e) {
    int i = blockIdx.x * blockDim.x + threadIdx.x;
    if (i >= NE) return;
    int d;
    if (g_is64) d = (int)((const long long*)e)[(long long)NE + i];
    else        d = ((const int*)e)[NE + i];
    atomicAdd(&g_deg[d], 1);
}

__global__ void k_dinv() {
    int i = blockIdx.x * blockDim.x + threadIdx.x;
    if (i < NN) g_dinv[i] = rsqrtf((float)g_deg[i] + 2.0f);
}

// ---------------- xs = dinv * x, converted to half2 ----------------
__global__ void k_xs(const float2* __restrict__ x2) {
    long long t = (long long)blockIdx.x * blockDim.x + threadIdx.x;
    if (t >= (long long)NN * 64) return;
    int node = (int)(t >> 6);
    float s = g_dinv[node];
    float2 v = __ldcs(&x2[t]);
    g_xsh[t] = __floats2half2_rn(v.x * s, v.y * s);
}

// ---------------- prefix scan of degrees (3 phases) ----------------
__global__ void k_scan1() {
    __shared__ int sbuf[SCAN_B];
    int tid = threadIdx.x;
    int i = blockIdx.x * SCAN_B + tid;
    int v = (i < NN) ? g_deg[i] : 0;
    sbuf[tid] = v;
    __syncthreads();
#pragma unroll
    for (int ofs = 1; ofs < SCAN_B; ofs <<= 1) {
        int t = (tid >= ofs) ? sbuf[tid - ofs] : 0;
        __syncthreads();
        sbuf[tid] += t;
        __syncthreads();
    }
    g_scan[blockIdx.x * SCAN_B + tid] = sbuf[tid];
    if (tid == SCAN_B - 1) g_bsum[blockIdx.x] = sbuf[tid];
}

__global__ void k_scan2() {
    if (threadIdx.x == 0) {
        int run = 0;
        for (int b = 0; b < NB; b++) { g_boff[b] = run; run += g_bsum[b]; }
    }
}

__global__ void k_scan3() {
    int i = blockIdx.x * blockDim.x + threadIdx.x;
    if (i < NN) g_off[i] = g_scan[i] - g_deg[i] + g_boff[i >> 10];  // exclusive
    if (i == NN) g_off[NN] = NE;
}

// ---------------- fill CSR: group edge srcs by dst ----------------
__global__ void k_fill(const void* __restrict__ e) {
    int i = blockIdx.x * blockDim.x + threadIdx.x;
    if (i >= NE) return;
    int s, d;
    if (g_is64) {
        s = (int)((const long long*)e)[i];
        d = (int)((const long long*)e)[(long long)NE + i];
    } else {
        s = ((const int*)e)[i];
        d = ((const int*)e)[NE + i];
    }
    int pos = atomicAdd(&g_cur[d], 1);
    g_csr[g_off[d] + pos] = s;
}

// ---------------- gather: one warp per dst node; fp16 reads, fp32 accum --
__device__ __forceinline__ void acc_h2pair(float4& a, uint2 raw) {
    float2 f0 = __half22float2(*reinterpret_cast<const __half2*>(&raw.x));
    float2 f1 = __half22float2(*reinterpret_cast<const __half2*>(&raw.y));
    a.x += f0.x; a.y += f0.y; a.z += f1.x; a.w += f1.y;
}

__global__ void __launch_bounds__(256) k_gather() {
    int n = (blockIdx.x * blockDim.x + threadIdx.x) >> 5;
    int lane = threadIdx.x & 31;
    if (n >= NN) return;
    int j = g_off[n];
    int jend = g_off[n + 1];
    const uint2* xs = (const uint2*)g_xsh;     // 2 half2 per lane-slot
    float4 a0 = make_float4(0.f, 0.f, 0.f, 0.f);
    float4 a1 = make_float4(0.f, 0.f, 0.f, 0.f);
    // self term: 2 * xs[n]
    {
        uint2 raw = xs[(long long)n * 32 + lane];
        acc_h2pair(a0, raw);
        a0.x *= 2.f; a0.y *= 2.f; a0.z *= 2.f; a0.w *= 2.f;
    }
    for (; j + 4 <= jend; j += 4) {
        int s0 = __ldcs(&g_csr[j]);
        int s1 = __ldcs(&g_csr[j + 1]);
        int s2 = __ldcs(&g_csr[j + 2]);
        int s3 = __ldcs(&g_csr[j + 3]);
        uint2 r0 = xs[(long long)s0 * 32 + lane];
        uint2 r1 = xs[(long long)s1 * 32 + lane];
        uint2 r2 = xs[(long long)s2 * 32 + lane];
        uint2 r3 = xs[(long long)s3 * 32 + lane];
        acc_h2pair(a0, r0);
        acc_h2pair(a1, r1);
        acc_h2pair(a0, r2);
        acc_h2pair(a1, r3);
    }
    for (; j < jend; j++) {
        int s = __ldcs(&g_csr[j]);
        uint2 r = xs[(long long)s * 32 + lane];
        acc_h2pair(a1, r);
    }
    float di = g_dinv[n];
    float4 o;
    o.x = di * (a0.x + a1.x); o.y = di * (a0.y + a1.y);
    o.z = di * (a0.z + a1.z); o.w = di * (a0.w + a1.w);
    g_agg[(long long)n * 32 + lane] = o;
}

// ---------------- fused GEMM (agg @ [Wz'|Wh']) + gate epilogue ----------
// block = 256 threads -> 64 rows x 256 cols; f32x2 packed accumulators.
// thread (tx,ty): tx=tid&15, ty=tid>>4; rows ty*4+r;
// col pairs: z: u*32 + 2*tx (+1), u=0..3;  t: 128 + same.
#define BM 64
#define BK 8
__global__ void __launch_bounds__(256) k_gemm(
    const float* __restrict__ lzb, const float* __restrict__ lhb,
    const float* __restrict__ w2, const float* __restrict__ b2,
    float* __restrict__ out)
{
    __shared__ float sA[BK][BM];
    __shared__ float sB[BK][256];
    int tid = threadIdx.x;
    int tx = tid & 15;
    int ty = tid >> 4;
    int rowBase = blockIdx.x * BM;
    const float* A = (const float*)g_agg;

    float2 accZ[4][4], accT[4][4];
#pragma unroll
    for (int r = 0; r < 4; r++)
#pragma unroll
        for (int u = 0; u < 4; u++) {
            accZ[r][u] = make_float2(0.f, 0.f);
            accT[r][u] = make_float2(0.f, 0.f);
        }

    for (int k0 = 0; k0 < DH; k0 += BK) {
        {
            int m = tid >> 2;
            int kk = (tid & 3) * 2;
            int gm = rowBase + m;
            float2 av = make_float2(0.f, 0.f);
            if (gm < NN) av = *(const float2*)&A[(long long)gm * DH + k0 + kk];
            sA[kk][m] = av.x;
            sA[kk + 1][m] = av.y;
        }
        {
#pragma unroll
            for (int i = 0; i < 2; i++) {
                int t = tid * 2 + i;
                int kk = t >> 6;
                int jj = (t & 63) * 4;
                float4 bv = *(const float4*)&g_wp[(k0 + kk) * 256 + jj];
                *(float4*)&sB[kk][jj] = bv;
            }
        }
        __syncthreads();
#pragma unroll
        for (int k = 0; k < BK; k++) {
            float2 ap[4];
#pragma unroll
            for (int r = 0; r < 4; r++) {
                float a = sA[k][ty * 4 + r];
                ap[r] = make_float2(a, a);
            }
#pragma unroll
            for (int u = 0; u < 4; u++) {
                float2 bz = *(const float2*)&sB[k][u * 32 + 2 * tx];
                float2 bt = *(const float2*)&sB[k][128 + u * 32 + 2 * tx];
#pragma unroll
                for (int r = 0; r < 4; r++) {
                    ffma2(accZ[r][u], ap[r], bz);
                    ffma2(accT[r][u], ap[r], bt);
                }
            }
        }
        __syncthreads();
    }

    // epilogue: p[r] = sum_j (1-sigmoid(u_j+lzb_j)) * tanh(v_j+lhb_j) * w2_j
    float p[4] = {0.f, 0.f, 0.f, 0.f};
#pragma unroll
    for (int u = 0; u < 4; u++) {
        int jj = u * 32 + 2 * tx;
        float2 bzb = *(const float2*)&lzb[jj];
        float2 bhb = *(const float2*)&lhb[jj];
        float2 w   = *(const float2*)&w2[jj];
#pragma unroll
        for (int r = 0; r < 4; r++) {
            float z0 = __fdividef(1.f, 1.f + __expf(-(accZ[r][u].x + bzb.x)));
            float z1 = __fdividef(1.f, 1.f + __expf(-(accZ[r][u].y + bzb.y)));
            float t0 = tanhf(accT[r][u].x + bhb.x);
            float t1 = tanhf(accT[r][u].y + bhb.y);
            p[r] += (1.f - z0) * t0 * w.x + (1.f - z1) * t1 * w.y;
        }
    }
#pragma unroll
    for (int off = 8; off >= 1; off >>= 1)
#pragma unroll
        for (int r = 0; r < 4; r++)
            p[r] += __shfl_down_sync(0xffffffffu, p[r], off, 16);

    if (tx == 0) {
        float bb = b2[0];
#pragma unroll
        for (int r = 0; r < 4; r++) {
            int row = rowBase + ty * 4 + r;
            if (row < NN) out[row] = p[r] + bb;
        }
    }
}

// ---------------- launcher ----------------
// metadata order: x, edge_index, Wz, bz, Wr, br, Wh, bh,
//                 lzW, lzb, lrW, lrb, lhW, lhb, W2, b2
extern "C" void kernel_launch(void* const* d_in, const int* in_sizes, int n_in,
                              void* d_out, int out_size) {
    const float2* x2  = (const float2*)d_in[0];
    const void*   ei  = d_in[1];
    const float*  Wz  = (const float*)d_in[2];
    const float*  Wh  = (const float*)d_in[6];
    const float*  lzW = (const float*)d_in[8];
    const float*  lzb = (const float*)d_in[9];
    const float*  lhW = (const float*)d_in[12];
    const float*  lhb = (const float*)d_in[13];
    const float*  W2  = (const float*)d_in[14];
    const float*  b2  = (const float*)d_in[15];
    float* out = (float*)d_out;

    k_detect<<<1, 32>>>((const unsigned int*)ei);
    k_wp<<<dim3(DH, 2), DH>>>(Wz, lzW, Wh, lhW);
    k_zero<<<(NN + 255) / 256, 256>>>();
    k_deg<<<(NE + 255) / 256, 256>>>(ei);
    k_dinv<<<(NN + 255) / 256, 256>>>();
    k_xs<<<(NN * 64 + 255) / 256, 256>>>(x2);
    k_scan1<<<NB, SCAN_B>>>();
    k_scan2<<<1, 32>>>();
    k_scan3<<<(NN + 256) / 256, 256>>>();
    k_fill<<<(NE + 255) / 256, 256>>>(ei);
    k_gather<<<(NN * 32 + 255) / 256, 256>>>();
    k_gemm<<<(NN + BM - 1) / BM, 256>>>(lzb, lhb, W2, b2, out);
}

// round 5
// speedup vs baseline: 1.8303x; 1.1686x over previous
#include <cuda_runtime.h>
#include <cuda_fp16.h>
#include <cuda_bf16.h>
#include <math.h>
#include <stdint.h>

#define NN 100000
#define NE 1600000
#define DH 128
#define NTILES 782
#define NPAD (NTILES * 128)          // 100096
#define SCAN_B 1024
#define NB ((NN + SCAN_B - 1) / SCAN_B)

// ---------------- device scratch (no allocations allowed) ----------------
__device__ int     g_is64;
__device__ int     g_deg[NN];
__device__ int     g_cur[NN];
__device__ int     g_scan[NB * SCAN_B];
__device__ int     g_bsum[NB];
__device__ int     g_boff[NB];
__device__ int     g_off[NN + 1];
__device__ int     g_csr[NE];                         // src ids grouped by dst
__device__ float   g_dinv[NN];
__device__ __half2 g_xsh[(size_t)NN * 64];            // dinv-scaled x fp16, 25.6MB
__device__ __align__(16) __nv_bfloat16 g_ah[(size_t)NPAD * DH];  // agg hi bf16 (pad rows 0)
__device__ __align__(16) __nv_bfloat16 g_al[(size_t)NPAD * DH];  // agg lo bf16
__device__ __align__(16) unsigned char g_bimg[131072]; // [Bh | Bl], [n][k] swizzled

// ---------------- helpers ----------------
__device__ __forceinline__ uint32_t smem_u32(const void* p) {
    uint32_t a;
    asm("{ .reg .u64 t; cvta.to.shared.u64 t, %1; cvt.u32.u64 %0, t; }" : "=r"(a) : "l"(p));
    return a;
}

#define LDSM4(r, addr) \
    asm volatile("ldmatrix.sync.aligned.m8n8.x4.shared.b16 {%0,%1,%2,%3}, [%4];" \
        : "=r"((r)[0]), "=r"((r)[1]), "=r"((r)[2]), "=r"((r)[3]) : "r"(addr))

#define MMA16816(c, a, b0v, b1v) \
    asm volatile("mma.sync.aligned.m16n8k16.row.col.f32.bf16.bf16.f32 " \
        "{%0,%1,%2,%3}, {%4,%5,%6,%7}, {%8,%9}, {%0,%1,%2,%3};" \
        : "+f"((c)[0]), "+f"((c)[1]), "+f"((c)[2]), "+f"((c)[3]) \
        : "r"((a)[0]), "r"((a)[1]), "r"((a)[2]), "r"((a)[3]), "r"(b0v), "r"(b1v))

// ---------------- dtype detection for edge_index (int64 vs int32) --------
__global__ void k_detect(const unsigned int* __restrict__ e) {
    if (threadIdx.x == 0) {
        int ok = 1;
#pragma unroll
        for (int i = 0; i < 64; i++) ok &= (e[2 * i + 1] == 0u);
        g_is64 = ok;
    }
}

// ------- fold weights -> split-bf16 B image, z/t column-interleaved ------
// output col n: n=2j   -> z_j = (Wz @ lzW[:128])[k][j]
//               n=2j+1 -> t_j = (Wh @ lhW[:128])[k][j]
// stored [n][k] row-major (256B rows), 16B-chunk XOR swizzle: chunk ^= (n&7)
__global__ void k_wp(const float* __restrict__ Wz, const float* __restrict__ lzW,
                     const float* __restrict__ Wh, const float* __restrict__ lhW) {
    int k = blockIdx.x;        // 0..127 (GEMM K dim)
    int half = blockIdx.y;     // 0: z, 1: t
    int j = threadIdx.x;       // 0..127
    const float* W = half ? Wh : Wz;
    const float* L = half ? lhW : lzW;
    float acc = 0.f;
#pragma unroll 4
    for (int c = 0; c < DH; c++) acc += W[k * DH + c] * L[c * DH + j];
    __nv_bfloat16 hi = __float2bfloat16(acc);
    __nv_bfloat16 lo = __float2bfloat16(acc - __bfloat162float(hi));
    int n = 2 * j + half;
    int off = n * 256 + (((k >> 3) ^ (n & 7)) << 4) + (k & 7) * 2;
    *(__nv_bfloat16*)(g_bimg + off) = hi;
    *(__nv_bfloat16*)(g_bimg + 65536 + off) = lo;
}

// ---------------- init counters ----------------
__global__ void k_zero() {
    int i = blockIdx.x * blockDim.x + threadIdx.x;
    if (i < NN) { g_deg[i] = 0; g_cur[i] = 0; }
}

// ---------------- degree (dst only) ----------------
__global__ void k_deg(const void* __restrict__ e) {
    int i = blockIdx.x * blockDim.x + threadIdx.x;
    if (i >= NE) return;
    int d;
    if (g_is64) d = (int)((const long long*)e)[(long long)NE + i];
    else        d = ((const int*)e)[NE + i];
    atomicAdd(&g_deg[d], 1);
}

__global__ void k_dinv() {
    int i = blockIdx.x * blockDim.x + threadIdx.x;
    if (i < NN) g_dinv[i] = rsqrtf((float)g_deg[i] + 2.0f);
}

// ---------------- xs = dinv * x, converted to half2 ----------------
__global__ void k_xs(const float2* __restrict__ x2) {
    long long t = (long long)blockIdx.x * blockDim.x + threadIdx.x;
    if (t >= (long long)NN * 64) return;
    int node = (int)(t >> 6);
    float s = g_dinv[node];
    float2 v = __ldcs(&x2[t]);
    g_xsh[t] = __floats2half2_rn(v.x * s, v.y * s);
}

// ---------------- prefix scan of degrees (3 phases) ----------------
__global__ void k_scan1() {
    __shared__ int sbuf[SCAN_B];
    int tid = threadIdx.x;
    int i = blockIdx.x * SCAN_B + tid;
    int v = (i < NN) ? g_deg[i] : 0;
    sbuf[tid] = v;
    __syncthreads();
#pragma unroll
    for (int ofs = 1; ofs < SCAN_B; ofs <<= 1) {
        int t = (tid >= ofs) ? sbuf[tid - ofs] : 0;
        __syncthreads();
        sbuf[tid] += t;
        __syncthreads();
    }
    g_scan[blockIdx.x * SCAN_B + tid] = sbuf[tid];
    if (tid == SCAN_B - 1) g_bsum[blockIdx.x] = sbuf[tid];
}

__global__ void k_scan2() {
    if (threadIdx.x == 0) {
        int run = 0;
        for (int b = 0; b < NB; b++) { g_boff[b] = run; run += g_bsum[b]; }
    }
}

__global__ void k_scan3() {
    int i = blockIdx.x * blockDim.x + threadIdx.x;
    if (i < NN) g_off[i] = g_scan[i] - g_deg[i] + g_boff[i >> 10];
    if (i == NN) g_off[NN] = NE;
}

// ---------------- fill CSR ----------------
__global__ void k_fill(const void* __restrict__ e) {
    int i = blockIdx.x * blockDim.x + threadIdx.x;
    if (i >= NE) return;
    int s, d;
    if (g_is64) {
        s = (int)((const long long*)e)[i];
        d = (int)((const long long*)e)[(long long)NE + i];
    } else {
        s = ((const int*)e)[i];
        d = ((const int*)e)[NE + i];
    }
    int pos = atomicAdd(&g_cur[d], 1);
    g_csr[g_off[d] + pos] = s;
}

// ---------------- gather -> split bf16 hi/lo ----------------
__device__ __forceinline__ void acc_h2pair(float4& a, uint2 raw) {
    float2 f0 = __half22float2(*reinterpret_cast<const __half2*>(&raw.x));
    float2 f1 = __half22float2(*reinterpret_cast<const __half2*>(&raw.y));
    a.x += f0.x; a.y += f0.y; a.z += f1.x; a.w += f1.y;
}

__device__ __forceinline__ uint32_t pack_hi(float a, float b, float& ra, float& rb) {
    __nv_bfloat16 ha = __float2bfloat16(a), hb = __float2bfloat16(b);
    ra = a - __bfloat162float(ha);
    rb = b - __bfloat162float(hb);
    union { __nv_bfloat162 v; uint32_t u; } q;
    q.v = __nv_bfloat162(ha, hb);
    return q.u;
}
__device__ __forceinline__ uint32_t pack_lo(float a, float b) {
    union { __nv_bfloat162 v; uint32_t u; } q;
    q.v = __nv_bfloat162(__float2bfloat16(a), __float2bfloat16(b));
    return q.u;
}

__global__ void __launch_bounds__(256) k_gather() {
    int n = (blockIdx.x * blockDim.x + threadIdx.x) >> 5;
    int lane = threadIdx.x & 31;
    if (n >= NN) return;
    int j = g_off[n];
    int jend = g_off[n + 1];
    const uint2* xs = (const uint2*)g_xsh;
    float4 a0 = make_float4(0.f, 0.f, 0.f, 0.f);
    float4 a1 = make_float4(0.f, 0.f, 0.f, 0.f);
    {
        uint2 raw = xs[(long long)n * 32 + lane];
        acc_h2pair(a0, raw);
        a0.x *= 2.f; a0.y *= 2.f; a0.z *= 2.f; a0.w *= 2.f;
    }
    for (; j + 4 <= jend; j += 4) {
        int s0 = __ldcs(&g_csr[j]);
        int s1 = __ldcs(&g_csr[j + 1]);
        int s2 = __ldcs(&g_csr[j + 2]);
        int s3 = __ldcs(&g_csr[j + 3]);
        uint2 r0 = xs[(long long)s0 * 32 + lane];
        uint2 r1 = xs[(long long)s1 * 32 + lane];
        uint2 r2 = xs[(long long)s2 * 32 + lane];
        uint2 r3 = xs[(long long)s3 * 32 + lane];
        acc_h2pair(a0, r0);
        acc_h2pair(a1, r1);
        acc_h2pair(a0, r2);
        acc_h2pair(a1, r3);
    }
    for (; j < jend; j++) {
        int s = __ldcs(&g_csr[j]);
        uint2 r = xs[(long long)s * 32 + lane];
        acc_h2pair(a1, r);
    }
    float di = g_dinv[n];
    float4 o;
    o.x = di * (a0.x + a1.x); o.y = di * (a0.y + a1.y);
    o.z = di * (a0.z + a1.z); o.w = di * (a0.w + a1.w);
    float r0, r1, r2, r3;
    uint2 H, L;
    H.x = pack_hi(o.x, o.y, r0, r1);
    H.y = pack_hi(o.z, o.w, r2, r3);
    L.x = pack_lo(r0, r1);
    L.y = pack_lo(r2, r3);
    size_t base = (size_t)n * DH + lane * 4;
    *(uint2*)&g_ah[base] = H;
    *(uint2*)&g_al[base] = L;
}

// ---------------- HMMA GEMM (mma.sync bf16) + gate epilogue -------------
// persistent, 512 threads (16 warps, 4m x 4n). Tile: 128 rows x 256 cols.
// D = Ah*Bh + Ah*Bl + Al*Bh (split-bf16). Output cols interleaved (2j=z_j, 2j+1=t_j)
// so each C-fragment (c0,c1)/(c2,c3) is a (z,t) pair -> register-local gates.
// smem: Bh[0,64K) Bl[64K,128K) Ah[128K,160K) Al[160K,192K) p_part[192K) biases
#define SM_BH 0
#define SM_BL 65536
#define SM_AH 131072
#define SM_AL 163840
#define SM_PP 196608
#define SM_ZB 198656
#define SM_HB 199168
#define SM_W2 199680
#define GEMM_SMEM 200704

__global__ void __launch_bounds__(512, 1) k_gemm(
    const float* __restrict__ lzb, const float* __restrict__ lhb,
    const float* __restrict__ w2, const float* __restrict__ b2,
    float* __restrict__ out)
{
    extern __shared__ unsigned char smem[];
    uint32_t sb = smem_u32(smem);
    int tid = threadIdx.x;
    int lane = tid & 31;
    int warp = tid >> 5;
    int wm = warp & 3, wn = warp >> 2;
    int m_base = wm * 32, n_base = wn * 64;
    int tid4 = lane & 3, grp = lane >> 2;

    float* p_part = (float*)(smem + SM_PP);
    float* szb = (float*)(smem + SM_ZB);
    float* shb = (float*)(smem + SM_HB);
    float* sw  = (float*)(smem + SM_W2);

    // load B image (pre-swizzled) + biases
    for (int i = tid * 16; i < 131072; i += 512 * 16)
        *(uint4*)(smem + i) = *(const uint4*)(g_bimg + i);
    if (tid < 128) { szb[tid] = lzb[tid]; shb[tid] = lhb[tid]; sw[tid] = w2[tid]; }
    float bbias = b2[0];
    __syncthreads();

    // ldmatrix lane address components
    int a_row = (lane & 7) | (((lane >> 3) & 1) << 3);   // 0..15 within m16 tile
    int a_ks  = lane >> 4;                                // k-chunk select 0/1
    int b_nrow = (lane & 7) | ((lane >> 4) << 3);         // 0..15 within n16 pair
    int b_ks  = (lane >> 3) & 1;
    int swz = lane & 7;
    uint32_t aRow0 = (uint32_t)(m_base + a_row) * 256;
    uint32_t aRow1 = (uint32_t)(m_base + 16 + a_row) * 256;
    uint32_t bRow[4];
#pragma unroll
    for (int q = 0; q < 4; q++) bRow[q] = (uint32_t)(n_base + q * 16 + b_nrow) * 256;

    for (int tile = blockIdx.x; tile < NTILES; tile += gridDim.x) {
        int rowBase = tile << 7;
        // stage Ah/Al tile into swizzled smem
        {
            const uint4* srcH = (const uint4*)(g_ah + (size_t)rowBase * DH);
            const uint4* srcL = (const uint4*)(g_al + (size_t)rowBase * DH);
#pragma unroll
            for (int it = 0; it < 4; it++) {
                int idx = tid + it * 512;          // 0..2047
                int row = idx >> 4, cc = idx & 15;
                uint32_t dst = row * 256 + ((cc ^ (row & 7)) << 4);
                *(uint4*)(smem + SM_AH + dst) = srcH[idx];
                *(uint4*)(smem + SM_AL + dst) = srcL[idx];
            }
        }
        __syncthreads();

        float c[2][8][4];
#pragma unroll
        for (int mt = 0; mt < 2; mt++)
#pragma unroll
            for (int nt = 0; nt < 8; nt++)
#pragma unroll
                for (int q = 0; q < 4; q++) c[mt][nt][q] = 0.f;

#pragma unroll
        for (int seg = 0; seg < 3; seg++) {
            uint32_t aS = sb + ((seg < 2) ? SM_AH : SM_AL);
            uint32_t bS = sb + ((seg == 1) ? SM_BL : SM_BH);
#pragma unroll
            for (int kt = 0; kt < 8; kt++) {
                int kc = kt * 2;
                uint32_t a0[4], a1[4], bfr[4][4];
                uint32_t aoff = (uint32_t)(((kc + a_ks) ^ swz) << 4);
                LDSM4(a0, aS + aRow0 + aoff);
                LDSM4(a1, aS + aRow1 + aoff);
                uint32_t boff = (uint32_t)(((kc + b_ks) ^ swz) << 4);
#pragma unroll
                for (int q = 0; q < 4; q++) LDSM4(bfr[q], bS + bRow[q] + boff);
#pragma unroll
                for (int nt = 0; nt < 8; nt++) {
                    uint32_t b0v = bfr[nt >> 1][(nt & 1) * 2];
                    uint32_t b1v = bfr[nt >> 1][(nt & 1) * 2 + 1];
                    MMA16816(c[0][nt], a0, b0v, b1v);
                    MMA16816(c[1][nt], a1, b0v, b1v);
                }
            }
        }

        // gate epilogue: term_j = (1-sigmoid(z_j+zb)) * tanh(t_j+hb) * w_j
        float pr[4] = {0.f, 0.f, 0.f, 0.f};   // [mt*2 + rowhalf]
#pragma unroll
        for (int nt = 0; nt < 8; nt++) {
            int jj = (n_base >> 1) + nt * 4 + tid4;
            float zb = szb[jj], hb = shb[jj], w = sw[jj];
#pragma unroll
            for (int mt = 0; mt < 2; mt++) {
                float uz = c[mt][nt][0] + zb;
                float s = __fdividef(1.f, 1.f + __expf(uz));
                float tv = c[mt][nt][1] + hb;
                float e2 = __expf(2.f * tv);
                float th = __fdividef(e2 - 1.f, e2 + 1.f);
                pr[mt * 2 + 0] += s * th * w;

                uz = c[mt][nt][2] + zb;
                s = __fdividef(1.f, 1.f + __expf(uz));
                tv = c[mt][nt][3] + hb;
                e2 = __expf(2.f * tv);
                th = __fdividef(e2 - 1.f, e2 + 1.f);
                pr[mt * 2 + 1] += s * th * w;
            }
        }
#pragma unroll
        for (int q = 0; q < 4; q++) {
            pr[q] += __shfl_xor_sync(0xffffffffu, pr[q], 1);
            pr[q] += __shfl_xor_sync(0xffffffffu, pr[q], 2);
        }
        if (tid4 == 0) {
            p_part[wn * 128 + m_base + grp]          = pr[0];
            p_part[wn * 128 + m_base + grp + 8]      = pr[1];
            p_part[wn * 128 + m_base + 16 + grp]     = pr[2];
            p_part[wn * 128 + m_base + 16 + grp + 8] = pr[3];
        }
        __syncthreads();
        if (tid < 128) {
            int row = rowBase + tid;
            if (row < NN)
                out[row] = p_part[tid] + p_part[128 + tid] +
                           p_part[256 + tid] + p_part[384 + tid] + bbias;
        }
        __syncthreads();
    }
}

// ---------------- launcher ----------------
// metadata order: x, edge_index, Wz, bz, Wr, br, Wh, bh,
//                 lzW, lzb, lrW, lrb, lhW, lhb, W2, b2
extern "C" void kernel_launch(void* const* d_in, const int* in_sizes, int n_in,
                              void* d_out, int out_size) {
    const float2* x2  = (const float2*)d_in[0];
    const void*   ei  = d_in[1];
    const float*  Wz  = (const float*)d_in[2];
    const float*  Wh  = (const float*)d_in[6];
    const float*  lzW = (const float*)d_in[8];
    const float*  lzb = (const float*)d_in[9];
    const float*  lhW = (const float*)d_in[12];
    const float*  lhb = (const float*)d_in[13];
    const float*  W2  = (const float*)d_in[14];
    const float*  b2  = (const float*)d_in[15];
    float* out = (float*)d_out;

    cudaFuncSetAttribute(k_gemm, cudaFuncAttributeMaxDynamicSharedMemorySize, GEMM_SMEM);

    k_detect<<<1, 32>>>((const unsigned int*)ei);
    k_wp<<<dim3(DH, 2), DH>>>(Wz, lzW, Wh, lhW);
    k_zero<<<(NN + 255) / 256, 256>>>();
    k_deg<<<(NE + 255) / 256, 256>>>(ei);
    k_dinv<<<(NN + 255) / 256, 256>>>();
    k_xs<<<(NN * 64 + 255) / 256, 256>>>(x2);
    k_scan1<<<NB, SCAN_B>>>();
    k_scan2<<<1, 32>>>();
    k_scan3<<<(NN + 256) / 256, 256>>>();
    k_fill<<<(NE + 255) / 256, 256>>>(ei);
    k_gather<<<(NN * 32 + 255) / 256, 256>>>();
    k_gemm<<<148, 512, GEMM_SMEM>>>(lzb, lhb, W2, b2, out);
}

// round 6
// speedup vs baseline: 2.7422x; 1.4982x over previous
#include <cuda_runtime.h>
#include <cuda_fp16.h>
#include <cuda_bf16.h>
#include <math.h>
#include <stdint.h>

#define NN 100000
#define NE 1600000
#define DH 128
#define NTILES 782
#define NPAD (NTILES * 128)          // 100096
#define SCAN_B 1024
#define NB ((NN + SCAN_B - 1) / SCAN_B)

// ---------------- device scratch (no allocations allowed) ----------------
__device__ int     g_is64;
__device__ int     g_deg[NN];
__device__ int     g_cur[NN];
__device__ int     g_scan[NB * SCAN_B];
__device__ int     g_bsum[NB];
__device__ int     g_boff[NB];
__device__ int     g_off[NN + 1];
__device__ int     g_csr[NE];                         // src ids grouped by dst
__device__ float   g_dinv[NN];
__device__ __half2 g_xsh[(size_t)NN * 64];            // dinv-scaled x fp16, 25.6MB
__device__ __align__(16) __half g_af[(size_t)NPAD * DH];   // agg fp16 (pad rows 0)
__device__ __align__(16) unsigned char g_bimg[131072];     // [Bh | Bl] fp16, [n][k] swizzled

// ---------------- helpers ----------------
__device__ __forceinline__ uint32_t smem_u32(const void* p) {
    uint32_t a;
    asm("{ .reg .u64 t; cvta.to.shared.u64 t, %1; cvt.u32.u64 %0, t; }" : "=r"(a) : "l"(p));
    return a;
}

#define LDSM4(r, addr) \
    asm volatile("ldmatrix.sync.aligned.m8n8.x4.shared.b16 {%0,%1,%2,%3}, [%4];" \
        : "=r"((r)[0]), "=r"((r)[1]), "=r"((r)[2]), "=r"((r)[3]) : "r"(addr))

#define MMA16816(c, a, b0v, b1v) \
    asm volatile("mma.sync.aligned.m16n8k16.row.col.f32.f16.f16.f32 " \
        "{%0,%1,%2,%3}, {%4,%5,%6,%7}, {%8,%9}, {%0,%1,%2,%3};" \
        : "+f"((c)[0]), "+f"((c)[1]), "+f"((c)[2]), "+f"((c)[3]) \
        : "r"((a)[0]), "r"((a)[1]), "r"((a)[2]), "r"((a)[3]), "r"(b0v), "r"(b1v))

#define CP_ASYNC16(dst, src) \
    asm volatile("cp.async.cg.shared.global [%0], [%1], 16;" :: "r"(dst), "l"(src))
#define CP_COMMIT  asm volatile("cp.async.commit_group;" ::: "memory")
#define CP_WAIT1   asm volatile("cp.async.wait_group 1;" ::: "memory")

// ---------------- dtype detection for edge_index (int64 vs int32) --------
__global__ void k_detect(const unsigned int* __restrict__ e) {
    if (threadIdx.x == 0) {
        int ok = 1;
#pragma unroll
        for (int i = 0; i < 64; i++) ok &= (e[2 * i + 1] == 0u);
        g_is64 = ok;
    }
}

// ------- fold weights -> split-fp16 B image, z/t column-interleaved ------
// col n: n=2j -> z_j = (Wz @ lzW[:128])[k][j]; n=2j+1 -> t_j = (Wh @ lhW)[k][j]
// stored [n][k] row-major (256B rows), 16B-chunk XOR swizzle: chunk ^= (n&7)
__global__ void k_wp(const float* __restrict__ Wz, const float* __restrict__ lzW,
                     const float* __restrict__ Wh, const float* __restrict__ lhW) {
    int k = blockIdx.x;        // 0..127 (GEMM K dim)
    int half = blockIdx.y;     // 0: z, 1: t
    int j = threadIdx.x;       // 0..127
    const float* W = half ? Wh : Wz;
    const float* L = half ? lhW : lzW;
    float acc = 0.f;
#pragma unroll 4
    for (int c = 0; c < DH; c++) acc += W[k * DH + c] * L[c * DH + j];
    __half hi = __float2half_rn(acc);
    __half lo = __float2half_rn(acc - __half2float(hi));
    int n = 2 * j + half;
    int off = n * 256 + (((k >> 3) ^ (n & 7)) << 4) + (k & 7) * 2;
    *(__half*)(g_bimg + off) = hi;
    *(__half*)(g_bimg + 65536 + off) = lo;
}

// ---------------- init counters ----------------
__global__ void k_zero() {
    int i = blockIdx.x * blockDim.x + threadIdx.x;
    if (i < NN) { g_deg[i] = 0; g_cur[i] = 0; }
}

// ---------------- degree (dst only) ----------------
__global__ void k_deg(const void* __restrict__ e) {
    int i = blockIdx.x * blockDim.x + threadIdx.x;
    if (i >= NE) return;
    int d;
    if (g_is64) d = (int)((const long long*)e)[(long long)NE + i];
    else        d = ((const int*)e)[NE + i];
    atomicAdd(&g_deg[d], 1);
}

__global__ void k_dinv() {
    int i = blockIdx.x * blockDim.x + threadIdx.x;
    if (i < NN) g_dinv[i] = rsqrtf((float)g_deg[i] + 2.0f);
}

// ---------------- xs = dinv * x, converted to half2 ----------------
__global__ void k_xs(const float2* __restrict__ x2) {
    long long t = (long long)blockIdx.x * blockDim.x + threadIdx.x;
    if (t >= (long long)NN * 64) return;
    int node = (int)(t >> 6);
    float s = g_dinv[node];
    float2 v = __ldcs(&x2[t]);
    g_xsh[t] = __floats2half2_rn(v.x * s, v.y * s);
}

// ---------------- prefix scan of degrees (3 phases) ----------------
__global__ void k_scan1() {
    __shared__ int sbuf[SCAN_B];
    int tid = threadIdx.x;
    int i = blockIdx.x * SCAN_B + tid;
    int v = (i < NN) ? g_deg[i] : 0;
    sbuf[tid] = v;
    __syncthreads();
#pragma unroll
    for (int ofs = 1; ofs < SCAN_B; ofs <<= 1) {
        int t = (tid >= ofs) ? sbuf[tid - ofs] : 0;
        __syncthreads();
        sbuf[tid] += t;
        __syncthreads();
    }
    g_scan[blockIdx.x * SCAN_B + tid] = sbuf[tid];
    if (tid == SCAN_B - 1) g_bsum[blockIdx.x] = sbuf[tid];
}

__global__ void k_scan2() {
    if (threadIdx.x == 0) {
        int run = 0;
        for (int b = 0; b < NB; b++) { g_boff[b] = run; run += g_bsum[b]; }
    }
}

__global__ void k_scan3() {
    int i = blockIdx.x * blockDim.x + threadIdx.x;
    if (i < NN) g_off[i] = g_scan[i] - g_deg[i] + g_boff[i >> 10];
    if (i == NN) g_off[NN] = NE;
}

// ---------------- fill CSR ----------------
__global__ void k_fill(const void* __restrict__ e) {
    int i = blockIdx.x * blockDim.x + threadIdx.x;
    if (i >= NE) return;
    int s, d;
    if (g_is64) {
        s = (int)((const long long*)e)[i];
        d = (int)((const long long*)e)[(long long)NE + i];
    } else {
        s = ((const int*)e)[i];
        d = ((const int*)e)[NE + i];
    }
    int pos = atomicAdd(&g_cur[d], 1);
    g_csr[g_off[d] + pos] = s;
}

// ---------------- gather -> fp16 A ----------------
__device__ __forceinline__ void acc_h2pair(float4& a, uint2 raw) {
    float2 f0 = __half22float2(*reinterpret_cast<const __half2*>(&raw.x));
    float2 f1 = __half22float2(*reinterpret_cast<const __half2*>(&raw.y));
    a.x += f0.x; a.y += f0.y; a.z += f1.x; a.w += f1.y;
}

__global__ void __launch_bounds__(256) k_gather() {
    int n = (blockIdx.x * blockDim.x + threadIdx.x) >> 5;
    int lane = threadIdx.x & 31;
    if (n >= NN) return;
    int j = g_off[n];
    int jend = g_off[n + 1];
    const uint2* xs = (const uint2*)g_xsh;
    float4 a0 = make_float4(0.f, 0.f, 0.f, 0.f);
    float4 a1 = make_float4(0.f, 0.f, 0.f, 0.f);
    {
        uint2 raw = xs[(long long)n * 32 + lane];
        acc_h2pair(a0, raw);
        a0.x *= 2.f; a0.y *= 2.f; a0.z *= 2.f; a0.w *= 2.f;
    }
    for (; j + 4 <= jend; j += 4) {
        int s0 = __ldcs(&g_csr[j]);
        int s1 = __ldcs(&g_csr[j + 1]);
        int s2 = __ldcs(&g_csr[j + 2]);
        int s3 = __ldcs(&g_csr[j + 3]);
        uint2 r0 = xs[(long long)s0 * 32 + lane];
        uint2 r1 = xs[(long long)s1 * 32 + lane];
        uint2 r2 = xs[(long long)s2 * 32 + lane];
        uint2 r3 = xs[(long long)s3 * 32 + lane];
        acc_h2pair(a0, r0);
        acc_h2pair(a1, r1);
        acc_h2pair(a0, r2);
        acc_h2pair(a1, r3);
    }
    for (; j < jend; j++) {
        int s = __ldcs(&g_csr[j]);
        uint2 r = xs[(long long)s * 32 + lane];
        acc_h2pair(a1, r);
    }
    float di = g_dinv[n];
    uint2 H;
    __half2 h0 = __floats2half2_rn(di * (a0.x + a1.x), di * (a0.y + a1.y));
    __half2 h1 = __floats2half2_rn(di * (a0.z + a1.z), di * (a0.w + a1.w));
    H.x = *reinterpret_cast<uint32_t*>(&h0);
    H.y = *reinterpret_cast<uint32_t*>(&h1);
    *(uint2*)&g_af[(size_t)n * DH + lane * 4] = H;
}

// ---------------- HMMA GEMM (mma.sync fp16) + gate epilogue -------------
// persistent, 512 threads (16 warps, 4m x 4n). Tile: 128 rows x 256 cols.
// D = A*Bh + A*Bl (A fp16 single, B split fp16). Output cols interleaved
// (2j=z_j, 2j+1=t_j) -> C-fragment pairs are (z,t) -> register-local gates.
// cp.async double-buffered A staging.
#define SM_BH 0
#define SM_BL 65536
#define SM_A0 131072
#define SM_A1 163840
#define SM_PP 196608
#define SM_ZB 198656
#define SM_HB 199168
#define SM_W2 199680
#define GEMM_SMEM 200704

__global__ void __launch_bounds__(512, 1) k_gemm(
    const float* __restrict__ lzb, const float* __restrict__ lhb,
    const float* __restrict__ w2, const float* __restrict__ b2,
    float* __restrict__ out)
{
    extern __shared__ unsigned char smem[];
    uint32_t sb = smem_u32(smem);
    int tid = threadIdx.x;
    int lane = tid & 31;
    int warp = tid >> 5;
    int wm = warp & 3, wn = warp >> 2;
    int m_base = wm * 32, n_base = wn * 64;
    int tid4 = lane & 3, grp = lane >> 2;

    float* p_part = (float*)(smem + SM_PP);
    float* szb = (float*)(smem + SM_ZB);
    float* shb = (float*)(smem + SM_HB);
    float* sw  = (float*)(smem + SM_W2);

    // load B image (pre-swizzled) + biases
    for (int i = tid * 16; i < 131072; i += 512 * 16)
        *(uint4*)(smem + i) = *(const uint4*)(g_bimg + i);
    if (tid < 128) { szb[tid] = lzb[tid]; shb[tid] = lhb[tid]; sw[tid] = w2[tid]; }
    float bbias = b2[0];

    // per-thread cp.async chunk indices (4 chunks of 16B per thread)
    // chunk idx: row = idx>>4 (0..127), cc = idx&15; dst swizzled by row&7
    uint32_t cp_dst[4];
    const __half* cp_src[4];
#pragma unroll
    for (int it = 0; it < 4; it++) {
        int idx = tid + it * 512;
        int row = idx >> 4, cc = idx & 15;
        cp_dst[it] = (uint32_t)(row * 256 + ((cc ^ (row & 7)) << 4));
        cp_src[it] = g_af + (size_t)row * DH + cc * 8;
    }

    // ldmatrix lane address components
    int a_row = (lane & 7) | (((lane >> 3) & 1) << 3);
    int a_ks  = lane >> 4;
    int b_nrow = (lane & 7) | ((lane >> 4) << 3);
    int b_ks  = (lane >> 3) & 1;
    int swz = lane & 7;
    uint32_t aRow0 = (uint32_t)(m_base + a_row) * 256;
    uint32_t aRow1 = (uint32_t)(m_base + 16 + a_row) * 256;
    uint32_t bRow[4];
#pragma unroll
    for (int q = 0; q < 4; q++) bRow[q] = (uint32_t)(n_base + q * 16 + b_nrow) * 256;

    // prologue prefetch: first tile into A0
    {
        size_t srcOfs = (size_t)(blockIdx.x << 7) * DH;
        uint32_t base = sb + SM_A0;
#pragma unroll
        for (int it = 0; it < 4; it++)
            CP_ASYNC16(base + cp_dst[it], cp_src[it] + srcOfs);
    }
    CP_COMMIT;
    __syncthreads();   // B image + biases ready

    int buf = 0;
    for (int tile = blockIdx.x; tile < NTILES; tile += gridDim.x) {
        int rowBase = tile << 7;
        // prefetch next tile into other buffer
        int nxt = tile + gridDim.x;
        if (nxt < NTILES) {
            size_t srcOfs = (size_t)(nxt << 7) * DH;
            uint32_t base = sb + (buf ? SM_A0 : SM_A1);
#pragma unroll
            for (int it = 0; it < 4; it++)
                CP_ASYNC16(base + cp_dst[it], cp_src[it] + srcOfs);
        }
        CP_COMMIT;
        CP_WAIT1;          // current tile's group complete
        __syncthreads();

        uint32_t aS = sb + (buf ? SM_A1 : SM_A0);

        float c[2][8][4];
#pragma unroll
        for (int mt = 0; mt < 2; mt++)
#pragma unroll
            for (int nt = 0; nt < 8; nt++)
#pragma unroll
                for (int q = 0; q < 4; q++) c[mt][nt][q] = 0.f;

#pragma unroll
        for (int kt = 0; kt < 8; kt++) {
            int kc = kt * 2;
            uint32_t a0[4], a1[4];
            uint32_t aoff = (uint32_t)(((kc + a_ks) ^ swz) << 4);
            LDSM4(a0, aS + aRow0 + aoff);
            LDSM4(a1, aS + aRow1 + aoff);
            uint32_t boff = (uint32_t)(((kc + b_ks) ^ swz) << 4);
#pragma unroll
            for (int seg = 0; seg < 2; seg++) {
                uint32_t bS = sb + (seg ? SM_BL : SM_BH);
                uint32_t bfr[4][4];
#pragma unroll
                for (int q = 0; q < 4; q++) LDSM4(bfr[q], bS + bRow[q] + boff);
#pragma unroll
                for (int nt = 0; nt < 8; nt++) {
                    uint32_t b0v = bfr[nt >> 1][(nt & 1) * 2];
                    uint32_t b1v = bfr[nt >> 1][(nt & 1) * 2 + 1];
                    MMA16816(c[0][nt], a0, b0v, b1v);
                    MMA16816(c[1][nt], a1, b0v, b1v);
                }
            }
        }

        // gate epilogue: term_j = (1-sigmoid(z_j+zb)) * tanh(t_j+hb) * w_j
        float pr[4] = {0.f, 0.f, 0.f, 0.f};
#pragma unroll
        for (int nt = 0; nt < 8; nt++) {
            int jj = (n_base >> 1) + nt * 4 + tid4;
            float zb = szb[jj], hb = shb[jj], w = sw[jj];
#pragma unroll
            for (int mt = 0; mt < 2; mt++) {
                float uz = c[mt][nt][0] + zb;
                float s = __fdividef(1.f, 1.f + __expf(uz));
                float tv = c[mt][nt][1] + hb;
                float e2 = __expf(2.f * tv);
                float th = __fdividef(e2 - 1.f, e2 + 1.f);
                pr[mt * 2 + 0] += s * th * w;

                uz = c[mt][nt][2] + zb;
                s = __fdividef(1.f, 1.f + __expf(uz));
                tv = c[mt][nt][3] + hb;
                e2 = __expf(2.f * tv);
                th = __fdividef(e2 - 1.f, e2 + 1.f);
                pr[mt * 2 + 1] += s * th * w;
            }
        }
#pragma unroll
        for (int q = 0; q < 4; q++) {
            pr[q] += __shfl_xor_sync(0xffffffffu, pr[q], 1);
            pr[q] += __shfl_xor_sync(0xffffffffu, pr[q], 2);
        }
        if (tid4 == 0) {
            p_part[wn * 128 + m_base + grp]          = pr[0];
            p_part[wn * 128 + m_base + grp + 8]      = pr[1];
            p_part[wn * 128 + m_base + 16 + grp]     = pr[2];
            p_part[wn * 128 + m_base + 16 + grp + 8] = pr[3];
        }
        __syncthreads();
        if (tid < 128) {
            int row = rowBase + tid;
            if (row < NN)
                out[row] = p_part[tid] + p_part[128 + tid] +
                           p_part[256 + tid] + p_part[384 + tid] + bbias;
        }
        __syncthreads();
        buf ^= 1;
    }
}

// ---------------- launcher ----------------
// metadata order: x, edge_index, Wz, bz, Wr, br, Wh, bh,
//                 lzW, lzb, lrW, lrb, lhW, lhb, W2, b2
extern "C" void kernel_launch(void* const* d_in, const int* in_sizes, int n_in,
                              void* d_out, int out_size) {
    const float2* x2  = (const float2*)d_in[0];
    const void*   ei  = d_in[1];
    const float*  Wz  = (const float*)d_in[2];
    const float*  Wh  = (const float*)d_in[6];
    const float*  lzW = (const float*)d_in[8];
    const float*  lzb = (const float*)d_in[9];
    const float*  lhW = (const float*)d_in[12];
    const float*  lhb = (const float*)d_in[13];
    const float*  W2  = (const float*)d_in[14];
    const float*  b2  = (const float*)d_in[15];
    float* out = (float*)d_out;

    cudaFuncSetAttribute(k_gemm, cudaFuncAttributeMaxDynamicSharedMemorySize, GEMM_SMEM);

    k_detect<<<1, 32>>>((const unsigned int*)ei);
    k_wp<<<dim3(DH, 2), DH>>>(Wz, lzW, Wh, lhW);
    k_zero<<<(NN + 255) / 256, 256>>>();
    k_deg<<<(NE + 255) / 256, 256>>>(ei);
    k_dinv<<<(NN + 255) / 256, 256>>>();
    k_xs<<<(NN * 64 + 255) / 256, 256>>>(x2);
    k_scan1<<<NB, SCAN_B>>>();
    k_scan2<<<1, 32>>>();
    k_scan3<<<(NN + 256) / 256, 256>>>();
    k_fill<<<(NE + 255) / 256, 256>>>(ei);
    k_gather<<<(NN * 32 + 255) / 256, 256>>>();
    k_gemm<<<148, 512, GEMM_SMEM>>>(lzb, lhb, W2, b2, out);
}

// round 7
// speedup vs baseline: 3.0043x; 1.0956x over previous
#include <cuda_runtime.h>
#include <cuda_fp16.h>
#include <math.h>
#include <stdint.h>

#define NN 100000
#define NE 1600000
#define DH 128
#define NTILES 782
#define NPAD (NTILES * 128)          // 100096
#define SCAN_B 1024
#define NB ((NN + SCAN_B - 1) / SCAN_B)

// ---------------- device scratch (no allocations allowed) ----------------
__device__ int     g_is64;
__device__ int     g_deg[NN];
__device__ int     g_cur[NN];
__device__ int     g_scan[NB * SCAN_B];
__device__ int     g_bsum[NB];
__device__ int     g_boff[NB];
__device__ int     g_off[NN + 1];
__device__ int     g_csr[NE];                         // src ids grouped by dst
__device__ float   g_dinv[NN];
__device__ __half2 g_xsh[(size_t)NN * 64];            // dinv-scaled x fp16, 25.6MB
__device__ __align__(16) __half g_af[(size_t)NPAD * DH];   // agg fp16 (pad rows 0)
__device__ __align__(16) unsigned char g_bimg[65536];      // B fp16, [n][k] swizzled

// ---------------- helpers ----------------
__device__ __forceinline__ uint32_t smem_u32(const void* p) {
    uint32_t a;
    asm("{ .reg .u64 t; cvta.to.shared.u64 t, %1; cvt.u32.u64 %0, t; }" : "=r"(a) : "l"(p));
    return a;
}

#define LDSM4(r, addr) \
    asm volatile("ldmatrix.sync.aligned.m8n8.x4.shared.b16 {%0,%1,%2,%3}, [%4];" \
        : "=r"((r)[0]), "=r"((r)[1]), "=r"((r)[2]), "=r"((r)[3]) : "r"(addr))

#define MMA16816(c, a, b0v, b1v) \
    asm volatile("mma.sync.aligned.m16n8k16.row.col.f32.f16.f16.f32 " \
        "{%0,%1,%2,%3}, {%4,%5,%6,%7}, {%8,%9}, {%0,%1,%2,%3};" \
        : "+f"((c)[0]), "+f"((c)[1]), "+f"((c)[2]), "+f"((c)[3]) \
        : "r"((a)[0]), "r"((a)[1]), "r"((a)[2]), "r"((a)[3]), "r"(b0v), "r"(b1v))

#define CP_ASYNC16(dst, src) \
    asm volatile("cp.async.cg.shared.global [%0], [%1], 16;" :: "r"(dst), "l"(src))
#define CP_COMMIT  asm volatile("cp.async.commit_group;" ::: "memory")
#define CP_WAIT1   asm volatile("cp.async.wait_group 1;" ::: "memory")

// ------- init counters + dtype detection (fused) --------------------------
__global__ void k_init(const unsigned int* __restrict__ e) {
    int i = blockIdx.x * blockDim.x + threadIdx.x;
    if (i < NN) { g_deg[i] = 0; g_cur[i] = 0; }
    if (i == 0) {
        int ok = 1;
#pragma unroll
        for (int q = 0; q < 64; q++) ok &= (e[2 * q + 1] == 0u);
        g_is64 = ok;   // all high words zero -> int64
    }
}

// ------- fold weights -> fp16 B image, z/t column-interleaved ------------
// col n: n=2j -> z_j = (Wz @ lzW[:128])[k][j]; n=2j+1 -> t_j = (Wh @ lhW)[k][j]
// stored [n][k] row-major (256B rows), 16B-chunk XOR swizzle: chunk ^= (n&7)
__global__ void k_wp(const float* __restrict__ Wz, const float* __restrict__ lzW,
                     const float* __restrict__ Wh, const float* __restrict__ lhW) {
    int k = blockIdx.x;        // 0..127 (GEMM K dim)
    int half = blockIdx.y;     // 0: z, 1: t
    int j = threadIdx.x;       // 0..127
    const float* W = half ? Wh : Wz;
    const float* L = half ? lhW : lzW;
    float acc = 0.f;
#pragma unroll 4
    for (int c = 0; c < DH; c++) acc += W[k * DH + c] * L[c * DH + j];
    int n = 2 * j + half;
    int off = n * 256 + (((k >> 3) ^ (n & 7)) << 4) + (k & 7) * 2;
    *(__half*)(g_bimg + off) = __float2half_rn(acc);
}

// ---------------- degree (dst only) ----------------
__global__ void k_deg(const void* __restrict__ e) {
    int i = blockIdx.x * blockDim.x + threadIdx.x;
    if (i >= NE) return;
    int d;
    if (g_is64) d = (int)((const long long*)e)[(long long)NE + i];
    else        d = ((const int*)e)[NE + i];
    atomicAdd(&g_deg[d], 1);
}

// ------- fused dinv + xs: warp per node ----------------------------------
__global__ void __launch_bounds__(256) k_dinvxs(const float2* __restrict__ x2) {
    int n = (blockIdx.x * blockDim.x + threadIdx.x) >> 5;
    int lane = threadIdx.x & 31;
    if (n >= NN) return;
    float di = 0.f;
    if (lane == 0) di = rsqrtf((float)g_deg[n] + 2.0f);
    di = __shfl_sync(0xffffffffu, di, 0);
    if (lane == 0) g_dinv[n] = di;
    const float2* src = x2 + (size_t)n * 64;
    __half2* dst = g_xsh + (size_t)n * 64;
#pragma unroll
    for (int i = 0; i < 2; i++) {
        float2 v = __ldcs(&src[lane + 32 * i]);
        dst[lane + 32 * i] = __floats2half2_rn(v.x * di, v.y * di);
    }
}

// ---------------- prefix scan of degrees (3 phases) ----------------
__global__ void k_scan1() {
    __shared__ int sbuf[SCAN_B];
    int tid = threadIdx.x;
    int i = blockIdx.x * SCAN_B + tid;
    int v = (i < NN) ? g_deg[i] : 0;
    sbuf[tid] = v;
    __syncthreads();
#pragma unroll
    for (int ofs = 1; ofs < SCAN_B; ofs <<= 1) {
        int t = (tid >= ofs) ? sbuf[tid - ofs] : 0;
        __syncthreads();
        sbuf[tid] += t;
        __syncthreads();
    }
    g_scan[blockIdx.x * SCAN_B + tid] = sbuf[tid];
    if (tid == SCAN_B - 1) g_bsum[blockIdx.x] = sbuf[tid];
}

__global__ void k_scan2() {
    if (threadIdx.x == 0) {
        int run = 0;
        for (int b = 0; b < NB; b++) { g_boff[b] = run; run += g_bsum[b]; }
    }
}

__global__ void k_scan3() {
    int i = blockIdx.x * blockDim.x + threadIdx.x;
    if (i < NN) g_off[i] = g_scan[i] - g_deg[i] + g_boff[i >> 10];
    if (i == NN) g_off[NN] = NE;
}

// ---------------- fill CSR ----------------
__global__ void k_fill(const void* __restrict__ e) {
    int i = blockIdx.x * blockDim.x + threadIdx.x;
    if (i >= NE) return;
    int s, d;
    if (g_is64) {
        s = (int)((const long long*)e)[i];
        d = (int)((const long long*)e)[(long long)NE + i];
    } else {
        s = ((const int*)e)[i];
        d = ((const int*)e)[NE + i];
    }
    int pos = atomicAdd(&g_cur[d], 1);
    g_csr[g_off[d] + pos] = s;
}

// ---------------- gather -> fp16 A ----------------
__device__ __forceinline__ void acc_h2pair(float4& a, uint2 raw) {
    float2 f0 = __half22float2(*reinterpret_cast<const __half2*>(&raw.x));
    float2 f1 = __half22float2(*reinterpret_cast<const __half2*>(&raw.y));
    a.x += f0.x; a.y += f0.y; a.z += f1.x; a.w += f1.y;
}

__global__ void __launch_bounds__(256) k_gather() {
    int n = (blockIdx.x * blockDim.x + threadIdx.x) >> 5;
    int lane = threadIdx.x & 31;
    if (n >= NN) return;
    int j = g_off[n];
    int jend = g_off[n + 1];
    const uint2* xs = (const uint2*)g_xsh;
    float4 a0 = make_float4(0.f, 0.f, 0.f, 0.f);
    float4 a1 = make_float4(0.f, 0.f, 0.f, 0.f);
    {
        uint2 raw = xs[(long long)n * 32 + lane];
        acc_h2pair(a0, raw);
        a0.x *= 2.f; a0.y *= 2.f; a0.z *= 2.f; a0.w *= 2.f;
    }
    for (; j + 4 <= jend; j += 4) {
        int s0 = __ldcs(&g_csr[j]);
        int s1 = __ldcs(&g_csr[j + 1]);
        int s2 = __ldcs(&g_csr[j + 2]);
        int s3 = __ldcs(&g_csr[j + 3]);
        uint2 r0 = xs[(long long)s0 * 32 + lane];
        uint2 r1 = xs[(long long)s1 * 32 + lane];
        uint2 r2 = xs[(long long)s2 * 32 + lane];
        uint2 r3 = xs[(long long)s3 * 32 + lane];
        acc_h2pair(a0, r0);
        acc_h2pair(a1, r1);
        acc_h2pair(a0, r2);
        acc_h2pair(a1, r3);
    }
    for (; j < jend; j++) {
        int s = __ldcs(&g_csr[j]);
        uint2 r = xs[(long long)s * 32 + lane];
        acc_h2pair(a1, r);
    }
    float di = g_dinv[n];
    uint2 H;
    __half2 h0 = __floats2half2_rn(di * (a0.x + a1.x), di * (a0.y + a1.y));
    __half2 h1 = __floats2half2_rn(di * (a0.z + a1.z), di * (a0.w + a1.w));
    H.x = *reinterpret_cast<uint32_t*>(&h0);
    H.y = *reinterpret_cast<uint32_t*>(&h1);
    *(uint2*)&g_af[(size_t)n * DH + lane * 4] = H;
}

// ---------------- HMMA GEMM (mma.sync fp16) + gate epilogue -------------
// persistent, 512 threads (16 warps, 4m x 4n). Tile: 128 rows x 256 cols.
// D = A*B (both fp16, fp32 accum). Output cols interleaved (2j=z_j, 2j+1=t_j)
// -> C-fragment pairs are (z,t) -> register-local gates.
// cp.async double-buffered A staging.
#define SM_B  0
#define SM_A0 65536
#define SM_A1 98304
#define SM_PP 131072
#define SM_ZB 133120
#define SM_HB 133632
#define SM_W2 134144
#define GEMM_SMEM 134656

__global__ void __launch_bounds__(512, 1) k_gemm(
    const float* __restrict__ lzb, const float* __restrict__ lhb,
    const float* __restrict__ w2, const float* __restrict__ b2,
    float* __restrict__ out)
{
    extern __shared__ unsigned char smem[];
    uint32_t sb = smem_u32(smem);
    int tid = threadIdx.x;
    int lane = tid & 31;
    int warp = tid >> 5;
    int wm = warp & 3, wn = warp >> 2;
    int m_base = wm * 32, n_base = wn * 64;
    int tid4 = lane & 3, grp = lane >> 2;

    float* p_part = (float*)(smem + SM_PP);
    float* szb = (float*)(smem + SM_ZB);
    float* shb = (float*)(smem + SM_HB);
    float* sw  = (float*)(smem + SM_W2);

    // load B image (pre-swizzled) + biases
    for (int i = tid * 16; i < 65536; i += 512 * 16)
        *(uint4*)(smem + i) = *(const uint4*)(g_bimg + i);
    if (tid < 128) { szb[tid] = lzb[tid]; shb[tid] = lhb[tid]; sw[tid] = w2[tid]; }
    float bbias = b2[0];

    // per-thread cp.async chunk indices (4 chunks of 16B per thread)
    uint32_t cp_dst[4];
    const __half* cp_src[4];
#pragma unroll
    for (int it = 0; it < 4; it++) {
        int idx = tid + it * 512;
        int row = idx >> 4, cc = idx & 15;
        cp_dst[it] = (uint32_t)(row * 256 + ((cc ^ (row & 7)) << 4));
        cp_src[it] = g_af + (size_t)row * DH + cc * 8;
    }

    // ldmatrix lane address components
    int a_row = (lane & 7) | (((lane >> 3) & 1) << 3);
    int a_ks  = lane >> 4;
    int b_nrow = (lane & 7) | ((lane >> 4) << 3);
    int b_ks  = (lane >> 3) & 1;
    int swz = lane & 7;
    uint32_t aRow0 = (uint32_t)(m_base + a_row) * 256;
    uint32_t aRow1 = (uint32_t)(m_base + 16 + a_row) * 256;
    uint32_t bRow[4];
#pragma unroll
    for (int q = 0; q < 4; q++) bRow[q] = (uint32_t)(n_base + q * 16 + b_nrow) * 256;

    // prologue prefetch: first tile into A0
    {
        size_t srcOfs = (size_t)(blockIdx.x << 7) * DH;
        uint32_t base = sb + SM_A0;
#pragma unroll
        for (int it = 0; it < 4; it++)
            CP_ASYNC16(base + cp_dst[it], cp_src[it] + srcOfs);
    }
    CP_COMMIT;
    __syncthreads();   // B image + biases ready

    int buf = 0;
    for (int tile = blockIdx.x; tile < NTILES; tile += gridDim.x) {
        int rowBase = tile << 7;
        // prefetch next tile into other buffer
        int nxt = tile + gridDim.x;
        if (nxt < NTILES) {
            size_t srcOfs = (size_t)(nxt << 7) * DH;
            uint32_t base = sb + (buf ? SM_A0 : SM_A1);
#pragma unroll
            for (int it = 0; it < 4; it++)
                CP_ASYNC16(base + cp_dst[it], cp_src[it] + srcOfs);
        }
        CP_COMMIT;
        CP_WAIT1;          // current tile's group complete
        __syncthreads();

        uint32_t aS = sb + (buf ? SM_A1 : SM_A0);
        uint32_t bS = sb + SM_B;

        float c[2][8][4];
#pragma unroll
        for (int mt = 0; mt < 2; mt++)
#pragma unroll
            for (int nt = 0; nt < 8; nt++)
#pragma unroll
                for (int q = 0; q < 4; q++) c[mt][nt][q] = 0.f;

#pragma unroll
        for (int kt = 0; kt < 8; kt++) {
            int kc = kt * 2;
            uint32_t a0[4], a1[4], bfr[4][4];
            uint32_t aoff = (uint32_t)(((kc + a_ks) ^ swz) << 4);
            LDSM4(a0, aS + aRow0 + aoff);
            LDSM4(a1, aS + aRow1 + aoff);
            uint32_t boff = (uint32_t)(((kc + b_ks) ^ swz) << 4);
#pragma unroll
            for (int q = 0; q < 4; q++) LDSM4(bfr[q], bS + bRow[q] + boff);
#pragma unroll
            for (int nt = 0; nt < 8; nt++) {
                uint32_t b0v = bfr[nt >> 1][(nt & 1) * 2];
                uint32_t b1v = bfr[nt >> 1][(nt & 1) * 2 + 1];
                MMA16816(c[0][nt], a0, b0v, b1v);
                MMA16816(c[1][nt], a1, b0v, b1v);
            }
        }

        // gate epilogue: term_j = (1-sigmoid(z_j+zb)) * tanh(t_j+hb) * w_j
        float pr[4] = {0.f, 0.f, 0.f, 0.f};
#pragma unroll
        for (int nt = 0; nt < 8; nt++) {
            int jj = (n_base >> 1) + nt * 4 + tid4;
            float zb = szb[jj], hb = shb[jj], w = sw[jj];
#pragma unroll
            for (int mt = 0; mt < 2; mt++) {
                float uz = c[mt][nt][0] + zb;
                float s = __fdividef(1.f, 1.f + __expf(uz));
                float tv = c[mt][nt][1] + hb;
                float e2 = __expf(2.f * tv);
                float th = __fdividef(e2 - 1.f, e2 + 1.f);
                pr[mt * 2 + 0] += s * th * w;

                uz = c[mt][nt][2] + zb;
                s = __fdividef(1.f, 1.f + __expf(uz));
                tv = c[mt][nt][3] + hb;
                e2 = __expf(2.f * tv);
                th = __fdividef(e2 - 1.f, e2 + 1.f);
                pr[mt * 2 + 1] += s * th * w;
            }
        }
#pragma unroll
        for (int q = 0; q < 4; q++) {
            pr[q] += __shfl_xor_sync(0xffffffffu, pr[q], 1);
            pr[q] += __shfl_xor_sync(0xffffffffu, pr[q], 2);
        }
        if (tid4 == 0) {
            p_part[wn * 128 + m_base + grp]          = pr[0];
            p_part[wn * 128 + m_base + grp + 8]      = pr[1];
            p_part[wn * 128 + m_base + 16 + grp]     = pr[2];
            p_part[wn * 128 + m_base + 16 + grp + 8] = pr[3];
        }
        __syncthreads();
        if (tid < 128) {
            int row = rowBase + tid;
            if (row < NN)
                out[row] = p_part[tid] + p_part[128 + tid] +
                           p_part[256 + tid] + p_part[384 + tid] + bbias;
        }
        __syncthreads();
        buf ^= 1;
    }
}

// ---------------- launcher ----------------
// metadata order: x, edge_index, Wz, bz, Wr, br, Wh, bh,
//                 lzW, lzb, lrW, lrb, lhW, lhb, W2, b2
extern "C" void kernel_launch(void* const* d_in, const int* in_sizes, int n_in,
                              void* d_out, int out_size) {
    const float2* x2  = (const float2*)d_in[0];
    const void*   ei  = d_in[1];
    const float*  Wz  = (const float*)d_in[2];
    const float*  Wh  = (const float*)d_in[6];
    const float*  lzW = (const float*)d_in[8];
    const float*  lzb = (const float*)d_in[9];
    const float*  lhW = (const float*)d_in[12];
    const float*  lhb = (const float*)d_in[13];
    const float*  W2  = (const float*)d_in[14];
    const float*  b2  = (const float*)d_in[15];
    float* out = (float*)d_out;

    cudaFuncSetAttribute(k_gemm, cudaFuncAttributeMaxDynamicSharedMemorySize, GEMM_SMEM);

    k_init<<<(NN + 255) / 256, 256>>>((const unsigned int*)ei);
    k_wp<<<dim3(DH, 2), DH>>>(Wz, lzW, Wh, lhW);
    k_deg<<<(NE + 255) / 256, 256>>>(ei);
    k_dinvxs<<<(NN * 32 + 255) / 256, 256>>>(x2);
    k_scan1<<<NB, SCAN_B>>>();
    k_scan2<<<1, 32>>>();
    k_scan3<<<(NN + 256) / 256, 256>>>();
    k_fill<<<(NE + 255) / 256, 256>>>(ei);
    k_gather<<<(NN * 32 + 255) / 256, 256>>>();
    k_gemm<<<148, 512, GEMM_SMEM>>>(lzb, lhb, W2, b2, out);
}

// round 8
// speedup vs baseline: 3.2141x; 1.0698x over previous
#include <cuda_runtime.h>
#include <cuda_fp16.h>
#include <math.h>
#include <stdint.h>

#define NN 100000
#define NE 1600000
#define DH 128
#define NTILES 782
#define NPAD (NTILES * 128)          // 100096
#define SCAN_B 1024
#define NB ((NN + SCAN_B - 1) / SCAN_B)

// ---------------- device scratch (no allocations allowed) ----------------
__device__ int     g_is64;
__device__ int     g_deg[NN];
__device__ int     g_cur[NN];
__device__ int     g_scan[NB * SCAN_B];
__device__ int     g_bsum[NB];
__device__ int     g_boff[NB];
__device__ int     g_off[NN + 1];
__device__ int     g_csr[NE];                         // src ids grouped by dst
__device__ float   g_dinv[NN];
__device__ __half2 g_xsh[(size_t)NN * 64];            // dinv-scaled x fp16, 25.6MB
__device__ __align__(16) __half g_af[(size_t)NPAD * DH];   // agg fp16 (pad rows 0)
__device__ __align__(16) unsigned char g_bimg[65536];      // B fp16, [n][k] swizzled

// ---------------- helpers ----------------
__device__ __forceinline__ uint32_t smem_u32(const void* p) {
    uint32_t a;
    asm("{ .reg .u64 t; cvta.to.shared.u64 t, %1; cvt.u32.u64 %0, t; }" : "=r"(a) : "l"(p));
    return a;
}

#define LDSM4(r, addr) \
    asm volatile("ldmatrix.sync.aligned.m8n8.x4.shared.b16 {%0,%1,%2,%3}, [%4];" \
        : "=r"((r)[0]), "=r"((r)[1]), "=r"((r)[2]), "=r"((r)[3]) : "r"(addr))

#define MMA16816(c, a, b0v, b1v) \
    asm volatile("mma.sync.aligned.m16n8k16.row.col.f32.f16.f16.f32 " \
        "{%0,%1,%2,%3}, {%4,%5,%6,%7}, {%8,%9}, {%0,%1,%2,%3};" \
        : "+f"((c)[0]), "+f"((c)[1]), "+f"((c)[2]), "+f"((c)[3]) \
        : "r"((a)[0]), "r"((a)[1]), "r"((a)[2]), "r"((a)[3]), "r"(b0v), "r"(b1v))

#define CP_ASYNC16(dst, src) \
    asm volatile("cp.async.cg.shared.global [%0], [%1], 16;" :: "r"(dst), "l"(src))
#define CP_COMMIT  asm volatile("cp.async.commit_group;" ::: "memory")
#define CP_WAIT1   asm volatile("cp.async.wait_group 1;" ::: "memory")

// ------- init counters + dtype detection (fused) --------------------------
__global__ void k_init(const unsigned int* __restrict__ e) {
    int i = blockIdx.x * blockDim.x + threadIdx.x;
    if (i < NN) { g_deg[i] = 0; g_cur[i] = 0; }
    if (i == 0) {
        int ok = 1;
#pragma unroll
        for (int q = 0; q < 64; q++) ok &= (e[2 * q + 1] == 0u);
        g_is64 = ok;   // all high words zero -> int64
    }
}

// ------- fold weights -> fp16 B image, z/t column-interleaved ------------
// col n: n=2j -> z_j = (Wz @ lzW[:128])[k][j]; n=2j+1 -> t_j = (Wh @ lhW)[k][j]
// stored [n][k] row-major (256B rows), 16B-chunk XOR swizzle: chunk ^= (n&7)
__global__ void k_wp(const float* __restrict__ Wz, const float* __restrict__ lzW,
                     const float* __restrict__ Wh, const float* __restrict__ lhW) {
    int k = blockIdx.x;        // 0..127 (GEMM K dim)
    int half = blockIdx.y;     // 0: z, 1: t
    int j = threadIdx.x;       // 0..127
    const float* W = half ? Wh : Wz;
    const float* L = half ? lhW : lzW;
    float acc = 0.f;
#pragma unroll 4
    for (int c = 0; c < DH; c++) acc += W[k * DH + c] * L[c * DH + j];
    int n = 2 * j + half;
    int off = n * 256 + (((k >> 3) ^ (n & 7)) << 4) + (k & 7) * 2;
    *(__half*)(g_bimg + off) = __float2half_rn(acc);
}

// ---------------- degree (dst only), 4 edges per thread -------------------
__global__ void k_deg(const void* __restrict__ e) {
    int t = blockIdx.x * blockDim.x + threadIdx.x;
    if (t >= NE / 4) return;
    int d0, d1, d2, d3;
    if (g_is64) {
        const ulonglong2* p = (const ulonglong2*)((const long long*)e + NE);
        ulonglong2 a = p[2 * t], b = p[2 * t + 1];
        d0 = (int)a.x; d1 = (int)a.y; d2 = (int)b.x; d3 = (int)b.y;
    } else {
        const int4* p = (const int4*)((const int*)e + NE);
        int4 a = p[t];
        d0 = a.x; d1 = a.y; d2 = a.z; d3 = a.w;
    }
    atomicAdd(&g_deg[d0], 1);
    atomicAdd(&g_deg[d1], 1);
    atomicAdd(&g_deg[d2], 1);
    atomicAdd(&g_deg[d3], 1);
}

// ------- fused dinv + xs: thread per 16B chunk, 4 independent iters -------
// DXCHUNKS = NN*32 = 3,200,000 float4 chunks; stride 800,000 -> exactly 4.
#define DX_STRIDE 800000
__global__ void __launch_bounds__(256) k_dinvxs(const float4* __restrict__ x4) {
    int base = blockIdx.x * blockDim.x + threadIdx.x;
#pragma unroll
    for (int k = 0; k < 4; k++) {
        int idx = base + k * DX_STRIDE;
        int node = idx >> 5;
        float di = rsqrtf((float)g_deg[node] + 2.0f);
        float4 v = __ldcs(&x4[idx]);
        __half2 h0 = __floats2half2_rn(v.x * di, v.y * di);
        __half2 h1 = __floats2half2_rn(v.z * di, v.w * di);
        uint2 o;
        o.x = *reinterpret_cast<uint32_t*>(&h0);
        o.y = *reinterpret_cast<uint32_t*>(&h1);
        *(uint2*)&g_xsh[(size_t)idx * 2] = o;
        if ((idx & 31) == 0) g_dinv[node] = di;
    }
}

// ---------------- prefix scan of degrees (3 phases) ----------------
__global__ void k_scan1() {
    __shared__ int sbuf[SCAN_B];
    int tid = threadIdx.x;
    int i = blockIdx.x * SCAN_B + tid;
    int v = (i < NN) ? g_deg[i] : 0;
    sbuf[tid] = v;
    __syncthreads();
#pragma unroll
    for (int ofs = 1; ofs < SCAN_B; ofs <<= 1) {
        int t = (tid >= ofs) ? sbuf[tid - ofs] : 0;
        __syncthreads();
        sbuf[tid] += t;
        __syncthreads();
    }
    g_scan[blockIdx.x * SCAN_B + tid] = sbuf[tid];
    if (tid == SCAN_B - 1) g_bsum[blockIdx.x] = sbuf[tid];
}

// parallel 128-thread scan over NB=98 block sums (was serial 1-thread!)
__global__ void k_scan2() {
    __shared__ int sb[128];
    int t = threadIdx.x;
    int v = (t < NB) ? g_bsum[t] : 0;
    sb[t] = v;
    __syncthreads();
#pragma unroll
    for (int o = 1; o < 128; o <<= 1) {
        int u = (t >= o) ? sb[t - o] : 0;
        __syncthreads();
        sb[t] += u;
        __syncthreads();
    }
    if (t < NB) g_boff[t] = sb[t] - v;   // exclusive prefix
}

__global__ void k_scan3() {
    int i = blockIdx.x * blockDim.x + threadIdx.x;
    if (i < NN) g_off[i] = g_scan[i] - g_deg[i] + g_boff[i >> 10];
    if (i == NN) g_off[NN] = NE;
}

// ---------------- fill CSR, 2 edges per thread ----------------
__global__ void k_fill(const void* __restrict__ e) {
    int t = blockIdx.x * blockDim.x + threadIdx.x;
    if (t >= NE / 2) return;
    int s0, s1, d0, d1;
    if (g_is64) {
        const ulonglong2* ps = (const ulonglong2*)e;
        const ulonglong2* pd = (const ulonglong2*)((const long long*)e + NE);
        ulonglong2 a = ps[t], b = pd[t];
        s0 = (int)a.x; s1 = (int)a.y; d0 = (int)b.x; d1 = (int)b.y;
    } else {
        const int2* ps = (const int2*)e;
        const int2* pd = (const int2*)((const int*)e + NE);
        int2 a = ps[t], b = pd[t];
        s0 = a.x; s1 = a.y; d0 = b.x; d1 = b.y;
    }
    int p0 = atomicAdd(&g_cur[d0], 1);
    g_csr[g_off[d0] + p0] = s0;
    int p1 = atomicAdd(&g_cur[d1], 1);
    g_csr[g_off[d1] + p1] = s1;
}

// ---------------- gather -> fp16 A ----------------
__device__ __forceinline__ void acc_h2pair(float4& a, uint2 raw) {
    float2 f0 = __half22float2(*reinterpret_cast<const __half2*>(&raw.x));
    float2 f1 = __half22float2(*reinterpret_cast<const __half2*>(&raw.y));
    a.x += f0.x; a.y += f0.y; a.z += f1.x; a.w += f1.y;
}

__global__ void __launch_bounds__(256) k_gather() {
    int n = (blockIdx.x * blockDim.x + threadIdx.x) >> 5;
    int lane = threadIdx.x & 31;
    if (n >= NN) return;
    int j = g_off[n];
    int jend = g_off[n + 1];
    const uint2* xs = (const uint2*)g_xsh;
    float4 a0 = make_float4(0.f, 0.f, 0.f, 0.f);
    float4 a1 = make_float4(0.f, 0.f, 0.f, 0.f);
    {
        uint2 raw = xs[(long long)n * 32 + lane];
        acc_h2pair(a0, raw);
        a0.x *= 2.f; a0.y *= 2.f; a0.z *= 2.f; a0.w *= 2.f;
    }
    for (; j + 4 <= jend; j += 4) {
        int s0 = __ldcs(&g_csr[j]);
        int s1 = __ldcs(&g_csr[j + 1]);
        int s2 = __ldcs(&g_csr[j + 2]);
        int s3 = __ldcs(&g_csr[j + 3]);
        uint2 r0 = xs[(long long)s0 * 32 + lane];
        uint2 r1 = xs[(long long)s1 * 32 + lane];
        uint2 r2 = xs[(long long)s2 * 32 + lane];
        uint2 r3 = xs[(long long)s3 * 32 + lane];
        acc_h2pair(a0, r0);
        acc_h2pair(a1, r1);
        acc_h2pair(a0, r2);
        acc_h2pair(a1, r3);
    }
    for (; j < jend; j++) {
        int s = __ldcs(&g_csr[j]);
        uint2 r = xs[(long long)s * 32 + lane];
        acc_h2pair(a1, r);
    }
    float di = g_dinv[n];
    uint2 H;
    __half2 h0 = __floats2half2_rn(di * (a0.x + a1.x), di * (a0.y + a1.y));
    __half2 h1 = __floats2half2_rn(di * (a0.z + a1.z), di * (a0.w + a1.w));
    H.x = *reinterpret_cast<uint32_t*>(&h0);
    H.y = *reinterpret_cast<uint32_t*>(&h1);
    *(uint2*)&g_af[(size_t)n * DH + lane * 4] = H;
}

// ---------------- HMMA GEMM (mma.sync fp16) + gate epilogue -------------
// persistent, 512 threads (16 warps, 4m x 4n). Tile: 128 rows x 256 cols.
// D = A*B (both fp16, fp32 accum). Output cols interleaved (2j=z_j, 2j+1=t_j)
// -> C-fragment pairs are (z,t) -> register-local gates.
// cp.async double-buffered A staging.
#define SM_B  0
#define SM_A0 65536
#define SM_A1 98304
#define SM_PP 131072
#define SM_ZB 133120
#define SM_HB 133632
#define SM_W2 134144
#define GEMM_SMEM 134656

__global__ void __launch_bounds__(512, 1) k_gemm(
    const float* __restrict__ lzb, const float* __restrict__ lhb,
    const float* __restrict__ w2, const float* __restrict__ b2,
    float* __restrict__ out)
{
    extern __shared__ unsigned char smem[];
    uint32_t sb = smem_u32(smem);
    int tid = threadIdx.x;
    int lane = tid & 31;
    int warp = tid >> 5;
    int wm = warp & 3, wn = warp >> 2;
    int m_base = wm * 32, n_base = wn * 64;
    int tid4 = lane & 3, grp = lane >> 2;

    float* p_part = (float*)(smem + SM_PP);
    float* szb = (float*)(smem + SM_ZB);
    float* shb = (float*)(smem + SM_HB);
    float* sw  = (float*)(smem + SM_W2);

    // load B image (pre-swizzled) + biases
    for (int i = tid * 16; i < 65536; i += 512 * 16)
        *(uint4*)(smem + i) = *(const uint4*)(g_bimg + i);
    if (tid < 128) { szb[tid] = lzb[tid]; shb[tid] = lhb[tid]; sw[tid] = w2[tid]; }
    float bbias = b2[0];

    // per-thread cp.async chunk indices (4 chunks of 16B per thread)
    uint32_t cp_dst[4];
    const __half* cp_src[4];
#pragma unroll
    for (int it = 0; it < 4; it++) {
        int idx = tid + it * 512;
        int row = idx >> 4, cc = idx & 15;
        cp_dst[it] = (uint32_t)(row * 256 + ((cc ^ (row & 7)) << 4));
        cp_src[it] = g_af + (size_t)row * DH + cc * 8;
    }

    // ldmatrix lane address components
    int a_row = (lane & 7) | (((lane >> 3) & 1) << 3);
    int a_ks  = lane >> 4;
    int b_nrow = (lane & 7) | ((lane >> 4) << 3);
    int b_ks  = (lane >> 3) & 1;
    int swz = lane & 7;
    uint32_t aRow0 = (uint32_t)(m_base + a_row) * 256;
    uint32_t aRow1 = (uint32_t)(m_base + 16 + a_row) * 256;
    uint32_t bRow[4];
#pragma unroll
    for (int q = 0; q < 4; q++) bRow[q] = (uint32_t)(n_base + q * 16 + b_nrow) * 256;

    // prologue prefetch: first tile into A0
    {
        size_t srcOfs = (size_t)(blockIdx.x << 7) * DH;
        uint32_t base = sb + SM_A0;
#pragma unroll
        for (int it = 0; it < 4; it++)
            CP_ASYNC16(base + cp_dst[it], cp_src[it] + srcOfs);
    }
    CP_COMMIT;
    __syncthreads();   // B image + biases ready

    int buf = 0;
    for (int tile = blockIdx.x; tile < NTILES; tile += gridDim.x) {
        int rowBase = tile << 7;
        // prefetch next tile into other buffer
        int nxt = tile + gridDim.x;
        if (nxt < NTILES) {
            size_t srcOfs = (size_t)(nxt << 7) * DH;
            uint32_t base = sb + (buf ? SM_A0 : SM_A1);
#pragma unroll
            for (int it = 0; it < 4; it++)
                CP_ASYNC16(base + cp_dst[it], cp_src[it] + srcOfs);
        }
        CP_COMMIT;
        CP_WAIT1;          // current tile's group complete
        __syncthreads();

        uint32_t aS = sb + (buf ? SM_A1 : SM_A0);
        uint32_t bS = sb + SM_B;

        float c[2][8][4];
#pragma unroll
        for (int mt = 0; mt < 2; mt++)
#pragma unroll
            for (int nt = 0; nt < 8; nt++)
#pragma unroll
                for (int q = 0; q < 4; q++) c[mt][nt][q] = 0.f;

#pragma unroll
        for (int kt = 0; kt < 8; kt++) {
            int kc = kt * 2;
            uint32_t a0[4], a1[4], bfr[4][4];
            uint32_t aoff = (uint32_t)(((kc + a_ks) ^ swz) << 4);
            LDSM4(a0, aS + aRow0 + aoff);
            LDSM4(a1, aS + aRow1 + aoff);
            uint32_t boff = (uint32_t)(((kc + b_ks) ^ swz) << 4);
#pragma unroll
            for (int q = 0; q < 4; q++) LDSM4(bfr[q], bS + bRow[q] + boff);
#pragma unroll
            for (int nt = 0; nt < 8; nt++) {
                uint32_t b0v = bfr[nt >> 1][(nt & 1) * 2];
                uint32_t b1v = bfr[nt >> 1][(nt & 1) * 2 + 1];
                MMA16816(c[0][nt], a0, b0v, b1v);
                MMA16816(c[1][nt], a1, b0v, b1v);
            }
        }

        // gate epilogue (single-div form):
        // (1-sigmoid(z)) * tanh(t) = (e^{2t} - 1) / ((1 + e^{z}) (e^{2t} + 1))
        float pr[4] = {0.f, 0.f, 0.f, 0.f};
#pragma unroll
        for (int nt = 0; nt < 8; nt++) {
            int jj = (n_base >> 1) + nt * 4 + tid4;
            float zb = szb[jj], hb = shb[jj], w = sw[jj];
#pragma unroll
            for (int mt = 0; mt < 2; mt++) {
                {
                    float eu = __expf(c[mt][nt][0] + zb);
                    float e2 = __expf(2.f * (c[mt][nt][1] + hb));
                    float term = __fdividef(e2 - 1.f, (1.f + eu) * (e2 + 1.f));
                    pr[mt * 2 + 0] += term * w;
                }
                {
                    float eu = __expf(c[mt][nt][2] + zb);
                    float e2 = __expf(2.f * (c[mt][nt][3] + hb));
                    float term = __fdividef(e2 - 1.f, (1.f + eu) * (e2 + 1.f));
                    pr[mt * 2 + 1] += term * w;
                }
            }
        }
#pragma unroll
        for (int q = 0; q < 4; q++) {
            pr[q] += __shfl_xor_sync(0xffffffffu, pr[q], 1);
            pr[q] += __shfl_xor_sync(0xffffffffu, pr[q], 2);
        }
        if (tid4 == 0) {
            p_part[wn * 128 + m_base + grp]          = pr[0];
            p_part[wn * 128 + m_base + grp + 8]      = pr[1];
            p_part[wn * 128 + m_base + 16 + grp]     = pr[2];
            p_part[wn * 128 + m_base + 16 + grp + 8] = pr[3];
        }
        __syncthreads();
        if (tid < 128) {
            int row = rowBase + tid;
            if (row < NN)
                out[row] = p_part[tid] + p_part[128 + tid] +
                           p_part[256 + tid] + p_part[384 + tid] + bbias;
        }
        __syncthreads();
        buf ^= 1;
    }
}

// ---------------- launcher ----------------
// metadata order: x, edge_index, Wz, bz, Wr, br, Wh, bh,
//                 lzW, lzb, lrW, lrb, lhW, lhb, W2, b2
extern "C" void kernel_launch(void* const* d_in, const int* in_sizes, int n_in,
                              void* d_out, int out_size) {
    const float4* x4  = (const float4*)d_in[0];
    const void*   ei  = d_in[1];
    const float*  Wz  = (const float*)d_in[2];
    const float*  Wh  = (const float*)d_in[6];
    const float*  lzW = (const float*)d_in[8];
    const float*  lzb = (const float*)d_in[9];
    const float*  lhW = (const float*)d_in[12];
    const float*  lhb = (const float*)d_in[13];
    const float*  W2  = (const float*)d_in[14];
    const float*  b2  = (const float*)d_in[15];
    float* out = (float*)d_out;

    cudaFuncSetAttribute(k_gemm, cudaFuncAttributeMaxDynamicSharedMemorySize, GEMM_SMEM);

    k_init<<<(NN + 255) / 256, 256>>>((const unsigned int*)ei);
    k_wp<<<dim3(DH, 2), DH>>>(Wz, lzW, Wh, lhW);
    k_deg<<<(NE / 4 + 255) / 256, 256>>>(ei);
    k_dinvxs<<<DX_STRIDE / 256, 256>>>(x4);
    k_scan1<<<NB, SCAN_B>>>();
    k_scan2<<<1, 128>>>();
    k_scan3<<<(NN + 256) / 256, 256>>>();
    k_fill<<<(NE / 2 + 255) / 256, 256>>>(ei);
    k_gather<<<(NN * 32 + 255) / 256, 256>>>();
    k_gemm<<<148, 512, GEMM_SMEM>>>(lzb, lhb, W2, b2, out);
}

// round 9
// speedup vs baseline: 3.2281x; 1.0044x over previous
#include <cuda_runtime.h>
#include <cuda_fp16.h>
#include <math.h>
#include <stdint.h>

#define NN 100000
#define NE 1600000
#define DH 128
#define NPAD 100096                  // padded rows (multiple of 128)
#define NT64 1564                    // NPAD / 64 tiles
#define SCAN_B 1024
#define NB ((NN + SCAN_B - 1) / SCAN_B)

// ---------------- device scratch (no allocations allowed) ----------------
__device__ int     g_is64;
__device__ int     g_deg[NN];
__device__ int     g_cur[NN];
__device__ int     g_scan[NB * SCAN_B];
__device__ int     g_bsum[NB];
__device__ int     g_boff[NB];
__device__ int     g_off[NN + 1];
__device__ int     g_csr[NE];                         // src ids grouped by dst
__device__ float   g_dinv[NN];
__device__ __half2 g_xsh[(size_t)NN * 64];            // dinv-scaled x fp16, 25.6MB
__device__ __align__(16) __half g_af[(size_t)NPAD * DH];   // agg fp16 (pad rows 0)
__device__ __align__(16) unsigned char g_bimg[65536];      // B fp16, [n][k] swizzled

// ---------------- helpers ----------------
__device__ __forceinline__ uint32_t smem_u32(const void* p) {
    uint32_t a;
    asm("{ .reg .u64 t; cvta.to.shared.u64 t, %1; cvt.u32.u64 %0, t; }" : "=r"(a) : "l"(p));
    return a;
}

#define LDSM4(r, addr) \
    asm volatile("ldmatrix.sync.aligned.m8n8.x4.shared.b16 {%0,%1,%2,%3}, [%4];" \
        : "=r"((r)[0]), "=r"((r)[1]), "=r"((r)[2]), "=r"((r)[3]) : "r"(addr))

#define MMA16816(c, a, b0v, b1v) \
    asm volatile("mma.sync.aligned.m16n8k16.row.col.f32.f16.f16.f32 " \
        "{%0,%1,%2,%3}, {%4,%5,%6,%7}, {%8,%9}, {%0,%1,%2,%3};" \
        : "+f"((c)[0]), "+f"((c)[1]), "+f"((c)[2]), "+f"((c)[3]) \
        : "r"((a)[0]), "r"((a)[1]), "r"((a)[2]), "r"((a)[3]), "r"(b0v), "r"(b1v))

#define CP_ASYNC16(dst, src) \
    asm volatile("cp.async.cg.shared.global [%0], [%1], 16;" :: "r"(dst), "l"(src))
#define CP_COMMIT  asm volatile("cp.async.commit_group;" ::: "memory")
#define CP_WAIT1   asm volatile("cp.async.wait_group 1;" ::: "memory")

// ------- init counters + dtype detection (fused) --------------------------
__global__ void k_init(const unsigned int* __restrict__ e) {
    int i = blockIdx.x * blockDim.x + threadIdx.x;
    if (i < NN) { g_deg[i] = 0; g_cur[i] = 0; }
    if (i == 0) {
        int ok = 1;
#pragma unroll
        for (int q = 0; q < 64; q++) ok &= (e[2 * q + 1] == 0u);
        g_is64 = ok;   // all high words zero -> int64
    }
}

// ------- fold weights -> fp16 B image, z/t column-interleaved ------------
// col n: n=2j -> z_j = (Wz @ lzW[:128])[k][j]; n=2j+1 -> t_j = (Wh @ lhW)[k][j]
// stored [n][k] row-major (256B rows), 16B-chunk XOR swizzle: chunk ^= (n&7)
__global__ void k_wp(const float* __restrict__ Wz, const float* __restrict__ lzW,
                     const float* __restrict__ Wh, const float* __restrict__ lhW) {
    int k = blockIdx.x;        // 0..127 (GEMM K dim)
    int half = blockIdx.y;     // 0: z, 1: t
    int j = threadIdx.x;       // 0..127
    const float* W = half ? Wh : Wz;
    const float* L = half ? lhW : lzW;
    float acc = 0.f;
#pragma unroll 4
    for (int c = 0; c < DH; c++) acc += W[k * DH + c] * L[c * DH + j];
    int n = 2 * j + half;
    int off = n * 256 + (((k >> 3) ^ (n & 7)) << 4) + (k & 7) * 2;
    *(__half*)(g_bimg + off) = __float2half_rn(acc);
}

// ---------------- degree (dst only), 4 edges per thread -------------------
__global__ void k_deg(const void* __restrict__ e) {
    int t = blockIdx.x * blockDim.x + threadIdx.x;
    if (t >= NE / 4) return;
    int d0, d1, d2, d3;
    if (g_is64) {
        const ulonglong2* p = (const ulonglong2*)((const long long*)e + NE);
        ulonglong2 a = p[2 * t], b = p[2 * t + 1];
        d0 = (int)a.x; d1 = (int)a.y; d2 = (int)b.x; d3 = (int)b.y;
    } else {
        const int4* p = (const int4*)((const int*)e + NE);
        int4 a = p[t];
        d0 = a.x; d1 = a.y; d2 = a.z; d3 = a.w;
    }
    atomicAdd(&g_deg[d0], 1);
    atomicAdd(&g_deg[d1], 1);
    atomicAdd(&g_deg[d2], 1);
    atomicAdd(&g_deg[d3], 1);
}

// ------- fused dinv + xs: thread per 16B chunk, 4 independent iters -------
#define DX_STRIDE 800000
__global__ void __launch_bounds__(256) k_dinvxs(const float4* __restrict__ x4) {
    int base = blockIdx.x * blockDim.x + threadIdx.x;
#pragma unroll
    for (int k = 0; k < 4; k++) {
        int idx = base + k * DX_STRIDE;
        int node = idx >> 5;
        float di = rsqrtf((float)g_deg[node] + 2.0f);
        float4 v = __ldcs(&x4[idx]);
        __half2 h0 = __floats2half2_rn(v.x * di, v.y * di);
        __half2 h1 = __floats2half2_rn(v.z * di, v.w * di);
        uint2 o;
        o.x = *reinterpret_cast<uint32_t*>(&h0);
        o.y = *reinterpret_cast<uint32_t*>(&h1);
        *(uint2*)&g_xsh[(size_t)idx * 2] = o;
        if ((idx & 31) == 0) g_dinv[node] = di;
    }
}

// ---------------- prefix scan of degrees (3 phases) ----------------
__global__ void k_scan1() {
    __shared__ int sbuf[SCAN_B];
    int tid = threadIdx.x;
    int i = blockIdx.x * SCAN_B + tid;
    int v = (i < NN) ? g_deg[i] : 0;
    sbuf[tid] = v;
    __syncthreads();
#pragma unroll
    for (int ofs = 1; ofs < SCAN_B; ofs <<= 1) {
        int t = (tid >= ofs) ? sbuf[tid - ofs] : 0;
        __syncthreads();
        sbuf[tid] += t;
        __syncthreads();
    }
    g_scan[blockIdx.x * SCAN_B + tid] = sbuf[tid];
    if (tid == SCAN_B - 1) g_bsum[blockIdx.x] = sbuf[tid];
}

__global__ void k_scan2() {
    __shared__ int sb[128];
    int t = threadIdx.x;
    int v = (t < NB) ? g_bsum[t] : 0;
    sb[t] = v;
    __syncthreads();
#pragma unroll
    for (int o = 1; o < 128; o <<= 1) {
        int u = (t >= o) ? sb[t - o] : 0;
        __syncthreads();
        sb[t] += u;
        __syncthreads();
    }
    if (t < NB) g_boff[t] = sb[t] - v;   // exclusive prefix
}

__global__ void k_scan3() {
    int i = blockIdx.x * blockDim.x + threadIdx.x;
    if (i < NN) g_off[i] = g_scan[i] - g_deg[i] + g_boff[i >> 10];
    if (i == NN) g_off[NN] = NE;
}

// ---------------- fill CSR, 4 edges per thread ----------------
__global__ void k_fill(const void* __restrict__ e) {
    int t = blockIdx.x * blockDim.x + threadIdx.x;
    if (t >= NE / 4) return;
    int s0, s1, s2, s3, d0, d1, d2, d3;
    if (g_is64) {
        const ulonglong2* ps = (const ulonglong2*)e;
        const ulonglong2* pd = (const ulonglong2*)((const long long*)e + NE);
        ulonglong2 a0 = ps[2 * t], a1 = ps[2 * t + 1];
        ulonglong2 b0 = pd[2 * t], b1 = pd[2 * t + 1];
        s0 = (int)a0.x; s1 = (int)a0.y; s2 = (int)a1.x; s3 = (int)a1.y;
        d0 = (int)b0.x; d1 = (int)b0.y; d2 = (int)b1.x; d3 = (int)b1.y;
    } else {
        const int4* ps = (const int4*)e;
        const int4* pd = (const int4*)((const int*)e + NE);
        int4 a = ps[t], b = pd[t];
        s0 = a.x; s1 = a.y; s2 = a.z; s3 = a.w;
        d0 = b.x; d1 = b.y; d2 = b.z; d3 = b.w;
    }
    int p0 = atomicAdd(&g_cur[d0], 1); g_csr[g_off[d0] + p0] = s0;
    int p1 = atomicAdd(&g_cur[d1], 1); g_csr[g_off[d1] + p1] = s1;
    int p2 = atomicAdd(&g_cur[d2], 1); g_csr[g_off[d2] + p2] = s2;
    int p3 = atomicAdd(&g_cur[d3], 1); g_csr[g_off[d3] + p3] = s3;
}

// ---------------- gather -> fp16 A ----------------
__device__ __forceinline__ void acc_h2pair(float4& a, uint2 raw) {
    float2 f0 = __half22float2(*reinterpret_cast<const __half2*>(&raw.x));
    float2 f1 = __half22float2(*reinterpret_cast<const __half2*>(&raw.y));
    a.x += f0.x; a.y += f0.y; a.z += f1.x; a.w += f1.y;
}

__global__ void __launch_bounds__(256) k_gather() {
    int n = (blockIdx.x * blockDim.x + threadIdx.x) >> 5;
    int lane = threadIdx.x & 31;
    if (n >= NN) return;
    int j = g_off[n];
    int jend = g_off[n + 1];
    const uint2* xs = (const uint2*)g_xsh;
    float4 a0 = make_float4(0.f, 0.f, 0.f, 0.f);
    float4 a1 = make_float4(0.f, 0.f, 0.f, 0.f);
    {
        uint2 raw = xs[(long long)n * 32 + lane];
        acc_h2pair(a0, raw);
        a0.x *= 2.f; a0.y *= 2.f; a0.z *= 2.f; a0.w *= 2.f;
    }
    for (; j + 4 <= jend; j += 4) {
        int s0 = __ldcs(&g_csr[j]);
        int s1 = __ldcs(&g_csr[j + 1]);
        int s2 = __ldcs(&g_csr[j + 2]);
        int s3 = __ldcs(&g_csr[j + 3]);
        uint2 r0 = xs[(long long)s0 * 32 + lane];
        uint2 r1 = xs[(long long)s1 * 32 + lane];
        uint2 r2 = xs[(long long)s2 * 32 + lane];
        uint2 r3 = xs[(long long)s3 * 32 + lane];
        acc_h2pair(a0, r0);
        acc_h2pair(a1, r1);
        acc_h2pair(a0, r2);
        acc_h2pair(a1, r3);
    }
    for (; j < jend; j++) {
        int s = __ldcs(&g_csr[j]);
        uint2 r = xs[(long long)s * 32 + lane];
        acc_h2pair(a1, r);
    }
    float di = g_dinv[n];
    uint2 H;
    __half2 h0 = __floats2half2_rn(di * (a0.x + a1.x), di * (a0.y + a1.y));
    __half2 h1 = __floats2half2_rn(di * (a0.z + a1.z), di * (a0.w + a1.w));
    H.x = *reinterpret_cast<uint32_t*>(&h0);
    H.y = *reinterpret_cast<uint32_t*>(&h1);
    *(uint2*)&g_af[(size_t)n * DH + lane * 4] = H;
}

// ---------------- HMMA GEMM (mma.sync fp16) + gate epilogue -------------
// persistent, 256 threads (8 warps, 2m x 4n), 2 CTAs/SM for overlap.
// Tile: 64 rows x 256 cols. D = A*B. Output cols interleaved (2j=z_j, 2j+1=t_j)
// -> C-fragment pairs are (z,t) -> register-local gates.
// cp.async double-buffered A staging.
#define SM_B  0
#define SM_A0 65536
#define SM_A1 81920
#define SM_PP 98304
#define SM_ZB 99328
#define SM_HB 99840
#define SM_W2 100352
#define GEMM_SMEM 100864

__global__ void __launch_bounds__(256, 2) k_gemm(
    const float* __restrict__ lzb, const float* __restrict__ lhb,
    const float* __restrict__ w2, const float* __restrict__ b2,
    float* __restrict__ out)
{
    extern __shared__ unsigned char smem[];
    uint32_t sb = smem_u32(smem);
    int tid = threadIdx.x;
    int lane = tid & 31;
    int warp = tid >> 5;
    int wm = warp & 1, wn = warp >> 1;     // 2 m-tiles x 4 n-tiles
    int m_base = wm * 32, n_base = wn * 64;
    int tid4 = lane & 3, grp = lane >> 2;

    float* p_part = (float*)(smem + SM_PP);
    float* szb = (float*)(smem + SM_ZB);
    float* shb = (float*)(smem + SM_HB);
    float* sw  = (float*)(smem + SM_W2);

    // load B image (pre-swizzled) + biases
    for (int i = tid * 16; i < 65536; i += 256 * 16)
        *(uint4*)(smem + i) = *(const uint4*)(g_bimg + i);
    if (tid < 128) { szb[tid] = lzb[tid]; shb[tid] = lhb[tid]; sw[tid] = w2[tid]; }
    float bbias = b2[0];

    // per-thread cp.async chunk indices (4 chunks of 16B per thread; 64 rows)
    uint32_t cp_dst[4];
    const __half* cp_src[4];
#pragma unroll
    for (int it = 0; it < 4; it++) {
        int idx = tid + it * 256;         // 0..1023
        int row = idx >> 4, cc = idx & 15;
        cp_dst[it] = (uint32_t)(row * 256 + ((cc ^ (row & 7)) << 4));
        cp_src[it] = g_af + (size_t)row * DH + cc * 8;
    }

    // ldmatrix lane address components
    int a_row = (lane & 7) | (((lane >> 3) & 1) << 3);
    int a_ks  = lane >> 4;
    int b_nrow = (lane & 7) | ((lane >> 4) << 3);
    int b_ks  = (lane >> 3) & 1;
    int swz = lane & 7;
    uint32_t aRow0 = (uint32_t)(m_base + a_row) * 256;
    uint32_t aRow1 = (uint32_t)(m_base + 16 + a_row) * 256;
    uint32_t bRow[4];
#pragma unroll
    for (int q = 0; q < 4; q++) bRow[q] = (uint32_t)(n_base + q * 16 + b_nrow) * 256;

    // prologue prefetch: first tile into A0
    {
        size_t srcOfs = (size_t)(blockIdx.x << 6) * DH;
        uint32_t base = sb + SM_A0;
#pragma unroll
        for (int it = 0; it < 4; it++)
            CP_ASYNC16(base + cp_dst[it], cp_src[it] + srcOfs);
    }
    CP_COMMIT;
    __syncthreads();   // B image + biases ready

    int buf = 0;
    for (int tile = blockIdx.x; tile < NT64; tile += gridDim.x) {
        int rowBase = tile << 6;
        // prefetch next tile into other buffer
        int nxt = tile + gridDim.x;
        if (nxt < NT64) {
            size_t srcOfs = (size_t)(nxt << 6) * DH;
            uint32_t base = sb + (buf ? SM_A0 : SM_A1);
#pragma unroll
            for (int it = 0; it < 4; it++)
                CP_ASYNC16(base + cp_dst[it], cp_src[it] + srcOfs);
        }
        CP_COMMIT;
        CP_WAIT1;          // current tile's group complete
        __syncthreads();

        uint32_t aS = sb + (buf ? SM_A1 : SM_A0);
        uint32_t bS = sb + SM_B;

        float c[2][8][4];
#pragma unroll
        for (int mt = 0; mt < 2; mt++)
#pragma unroll
            for (int nt = 0; nt < 8; nt++)
#pragma unroll
                for (int q = 0; q < 4; q++) c[mt][nt][q] = 0.f;

#pragma unroll
        for (int kt = 0; kt < 8; kt++) {
            int kc = kt * 2;
            uint32_t a0[4], a1[4], bfr[4][4];
            uint32_t aoff = (uint32_t)(((kc + a_ks) ^ swz) << 4);
            LDSM4(a0, aS + aRow0 + aoff);
            LDSM4(a1, aS + aRow1 + aoff);
            uint32_t boff = (uint32_t)(((kc + b_ks) ^ swz) << 4);
#pragma unroll
            for (int q = 0; q < 4; q++) LDSM4(bfr[q], bS + bRow[q] + boff);
#pragma unroll
            for (int nt = 0; nt < 8; nt++) {
                uint32_t b0v = bfr[nt >> 1][(nt & 1) * 2];
                uint32_t b1v = bfr[nt >> 1][(nt & 1) * 2 + 1];
                MMA16816(c[0][nt], a0, b0v, b1v);
                MMA16816(c[1][nt], a1, b0v, b1v);
            }
        }

        // gate epilogue (single-div form):
        // (1-sigmoid(z)) * tanh(t) = (e^{2t} - 1) / ((1 + e^{z}) (e^{2t} + 1))
        float pr[4] = {0.f, 0.f, 0.f, 0.f};
#pragma unroll
        for (int nt = 0; nt < 8; nt++) {
            int jj = (n_base >> 1) + nt * 4 + tid4;
            float zb = szb[jj], hb = shb[jj], w = sw[jj];
#pragma unroll
            for (int mt = 0; mt < 2; mt++) {
                {
                    float eu = __expf(c[mt][nt][0] + zb);
                    float e2 = __expf(2.f * (c[mt][nt][1] + hb));
                    float term = __fdividef(e2 - 1.f, (1.f + eu) * (e2 + 1.f));
                    pr[mt * 2 + 0] += term * w;
                }
                {
                    float eu = __expf(c[mt][nt][2] + zb);
                    float e2 = __expf(2.f * (c[mt][nt][3] + hb));
                    float term = __fdividef(e2 - 1.f, (1.f + eu) * (e2 + 1.f));
                    pr[mt * 2 + 1] += term * w;
                }
            }
        }
#pragma unroll
        for (int q = 0; q < 4; q++) {
            pr[q] += __shfl_xor_sync(0xffffffffu, pr[q], 1);
            pr[q] += __shfl_xor_sync(0xffffffffu, pr[q], 2);
        }
        if (tid4 == 0) {
            p_part[wn * 64 + m_base + grp]          = pr[0];
            p_part[wn * 64 + m_base + grp + 8]      = pr[1];
            p_part[wn * 64 + m_base + 16 + grp]     = pr[2];
            p_part[wn * 64 + m_base + 16 + grp + 8] = pr[3];
        }
        __syncthreads();
        if (tid < 64) {
            int row = rowBase + tid;
            if (row < NN)
                out[row] = p_part[tid] + p_part[64 + tid] +
                           p_part[128 + tid] + p_part[192 + tid] + bbias;
        }
        __syncthreads();
        buf ^= 1;
    }
}

// ---------------- launcher ----------------
// metadata order: x, edge_index, Wz, bz, Wr, br, Wh, bh,
//                 lzW, lzb, lrW, lrb, lhW, lhb, W2, b2
extern "C" void kernel_launch(void* const* d_in, const int* in_sizes, int n_in,
                              void* d_out, int out_size) {
    const float4* x4  = (const float4*)d_in[0];
    const void*   ei  = d_in[1];
    const float*  Wz  = (const float*)d_in[2];
    const float*  Wh  = (const float*)d_in[6];
    const float*  lzW = (const float*)d_in[8];
    const float*  lzb = (const float*)d_in[9];
    const float*  lhW = (const float*)d_in[12];
    const float*  lhb = (const float*)d_in[13];
    const float*  W2  = (const float*)d_in[14];
    const float*  b2  = (const float*)d_in[15];
    float* out = (float*)d_out;

    cudaFuncSetAttribute(k_gemm, cudaFuncAttributeMaxDynamicSharedMemorySize, GEMM_SMEM);

    k_init<<<(NN + 255) / 256, 256>>>((const unsigned int*)ei);
    k_wp<<<dim3(DH, 2), DH>>>(Wz, lzW, Wh, lhW);
    k_deg<<<(NE / 4 + 255) / 256, 256>>>(ei);
    k_dinvxs<<<DX_STRIDE / 256, 256>>>(x4);
    k_scan1<<<NB, SCAN_B>>>();
    k_scan2<<<1, 128>>>();
    k_scan3<<<(NN + 256) / 256, 256>>>();
    k_fill<<<(NE / 4 + 255) / 256, 256>>>(ei);
    k_gather<<<(NN * 32 + 255) / 256, 256>>>();
    k_gemm<<<296, 256, GEMM_SMEM>>>(lzb, lhb, W2, b2, out);
}